// round 4
// baseline (speedup 1.0000x reference)
#include <cuda_runtime.h>
#include <math.h>

#define N_NODES  100000
#define N_EDGES  3200000
#define N_GRAPHS 64
#define F_IN     128
#define HID      256
#define N_CLS    2

// ---------------------------------------------------------------------------
// Scratch
// ---------------------------------------------------------------------------
__device__ __align__(16) float g_dinv[N_NODES];
__device__ __align__(16) int   g_deg[N_NODES];
__device__ __align__(16) int   g_rowptr[N_NODES + 1];
__device__ __align__(16) int   g_cursor[N_NODES];
__device__ __align__(16) int2  g_csr[N_EDGES];          // {src, dinv[src] bits}
__device__ __align__(16) float g_buf1[(size_t)N_NODES * HID];
__device__ __align__(16) float g_buf2[(size_t)N_NODES * HID];
__device__ __align__(16) float g_sums[N_GRAPHS * HID];
__device__ float g_cnt[N_GRAPHS];
__device__ int   g_is64;

// ---------------------------------------------------------------------------
__device__ __forceinline__ void red_add_v4(float* p, float4 v) {
    asm volatile("red.global.add.v4.f32 [%0], {%1, %2, %3, %4};"
                 :: "l"(p), "f"(v.x), "f"(v.y), "f"(v.z), "f"(v.w) : "memory");
}
__device__ __forceinline__ int idx_at(const void* p, long long i, int is64) {
    return is64 ? (int)((const long long*)p)[i] : ((const int*)p)[i];
}
__device__ __forceinline__ void fma4(float4& a, float4 v, float w) {
    a.x += v.x * w; a.y += v.y * w; a.z += v.z * w; a.w += v.w * w;
}

// ---------------------------------------------------------------------------
// (1) zero counters + detect index dtype
// ---------------------------------------------------------------------------
__global__ void k_zero(const void* __restrict__ edges) {
    int i = blockIdx.x * blockDim.x + threadIdx.x;
    if (i < N_NODES) g_deg[i] = 0;
    if (i < N_GRAPHS * HID) g_sums[i] = 0.0f;
    if (i < N_GRAPHS) g_cnt[i] = 0.0f;
    if (i == 0) {
        const long long* p = (const long long*)edges;
        int is64 = 1;
        for (int j = 0; j < 512; j++) {
            long long v = p[j];
            if (v < 0 || v >= N_NODES) { is64 = 0; break; }
        }
        g_is64 = is64;
    }
}

// (2) in-degree count + per-graph node count
__global__ void k_deg_cnt(const void* __restrict__ edges, const void* __restrict__ batch) {
    int i = blockIdx.x * blockDim.x + threadIdx.x;
    int is64 = g_is64;
    if (i < N_EDGES) {
        int d = idx_at(edges, (long long)N_EDGES + i, is64);
        atomicAdd(&g_deg[d], 1);
    }
    if (i < N_NODES) {
        int g = idx_at(batch, i, is64);
        atomicAdd(&g_cnt[g], 1.0f);
    }
}

// (3) single-block scan -> rowptr/cursor; dinv = rsqrt(deg+1)
__global__ void k_scan_rsqrt() {
    const int T = 1024;
    const int CH = (N_NODES + T - 1) / T;
    __shared__ int part[T];
    int t = threadIdx.x;
    int base = t * CH;
    int local = 0;
    for (int i = 0; i < CH; i++) {
        int idx = base + i;
        if (idx < N_NODES) local += g_deg[idx];
    }
    part[t] = local;
    __syncthreads();
    for (int off = 1; off < T; off <<= 1) {
        int v = (t >= off) ? part[t - off] : 0;
        __syncthreads();
        if (t >= off) part[t] += v;
        __syncthreads();
    }
    int prefix = (t == 0) ? 0 : part[t - 1];
    for (int i = 0; i < CH; i++) {
        int idx = base + i;
        if (idx < N_NODES) {
            g_rowptr[idx] = prefix;
            g_cursor[idx] = prefix;
            prefix += g_deg[idx];
        }
    }
    if (t == T - 1) g_rowptr[N_NODES] = part[T - 1];
    __syncthreads();
    for (int i = t; i < N_NODES; i += T)
        g_dinv[i] = rsqrtf((float)(g_deg[i] + 1));
}

// (5) CSR fill: {src, dinv[src]}   (dinv[dst] factored out, applied in agg)
__global__ void k_fill(const void* __restrict__ edges) {
    int e = blockIdx.x * blockDim.x + threadIdx.x;
    if (e >= N_EDGES) return;
    int is64 = g_is64;
    int s = idx_at(edges, e, is64);
    int d = idx_at(edges, (long long)N_EDGES + e, is64);
    int slot = atomicAdd(&g_cursor[d], 1);
    g_csr[slot] = make_int2(s, __float_as_int(g_dinv[s]));
}

// ---------------------------------------------------------------------------
// (4,7) Pure SGEMM: C[M,N] = A[M,K] @ W[K,N]   (no bias/relu — moved to agg)
// BM=128 BN=64 BK=16, 128 threads, 8x8/thread, A-tile transposed in smem.
// ---------------------------------------------------------------------------
__global__ void __launch_bounds__(128) k_gemm(
    const float* __restrict__ A, const float* __restrict__ W,
    float* __restrict__ C_, int M, int N, int K) {
    constexpr int BM = 128, BN = 64, BK = 16, TM = 8, TN = 8;
    constexpr int TX = BN / TN;   // 8
    __shared__ float Ast[BK][BM];
    __shared__ float Ws[BK][BN];

    const int tid = threadIdx.x;
    const int tx = tid % TX;
    const int ty = tid / TX;
    const int row0 = blockIdx.y * BM;
    const int col0 = blockIdx.x * BN;

    const int am = tid / 4;
    const int ak4 = tid % 4;
    const int wk = tid / 16;
    const int wn4 = tid % 16;

    float acc[TM][TN];
#pragma unroll
    for (int i = 0; i < TM; i++)
#pragma unroll
        for (int j = 0; j < TN; j++) acc[i][j] = 0.0f;

    for (int k0 = 0; k0 < K; k0 += BK) {
#pragma unroll
        for (int it = 0; it < 4; it++) {
            int gm = row0 + am + it * 32;
            float4 v = make_float4(0.f, 0.f, 0.f, 0.f);
            if (gm < M) v = *(const float4*)(A + (size_t)gm * K + k0 + ak4 * 4);
            int m = am + it * 32;
            Ast[ak4 * 4 + 0][m] = v.x;
            Ast[ak4 * 4 + 1][m] = v.y;
            Ast[ak4 * 4 + 2][m] = v.z;
            Ast[ak4 * 4 + 3][m] = v.w;
        }
#pragma unroll
        for (int it = 0; it < 2; it++) {
            int k = wk + it * 8;
            *(float4*)(&Ws[k][wn4 * 4]) =
                *(const float4*)(W + (size_t)(k0 + k) * N + col0 + wn4 * 4);
        }
        __syncthreads();
#pragma unroll
        for (int k = 0; k < BK; k++) {
            float4 a0 = *(const float4*)(&Ast[k][ty * TM]);
            float4 a1 = *(const float4*)(&Ast[k][ty * TM + 4]);
            float4 w0 = *(const float4*)(&Ws[k][tx * TN]);
            float4 w1 = *(const float4*)(&Ws[k][tx * TN + 4]);
            float av[TM] = {a0.x, a0.y, a0.z, a0.w, a1.x, a1.y, a1.z, a1.w};
            float wv[TN] = {w0.x, w0.y, w0.z, w0.w, w1.x, w1.y, w1.z, w1.w};
#pragma unroll
            for (int i = 0; i < TM; i++)
#pragma unroll
                for (int j = 0; j < TN; j++) acc[i][j] += av[i] * wv[j];
        }
        __syncthreads();
    }

#pragma unroll
    for (int i = 0; i < TM; i++) {
        int gm = row0 + ty * TM + i;
        if (gm >= M) continue;
        float* dst = C_ + (size_t)gm * N + col0 + tx * TN;
        *(float4*)(dst) = make_float4(acc[i][0], acc[i][1], acc[i][2], acc[i][3]);
        *(float4*)(dst + 4) = make_float4(acc[i][4], acc[i][5], acc[i][6], acc[i][7]);
    }
}

// ---------------------------------------------------------------------------
// (6,8) Pull aggregation, one WARP per node, F=256 (C=2 float4/lane):
//   r = relu( dinv_d * ( dinv_d*T[d] + sum_e dinv_s*T[src e] ) + b )
// MODE 0: write r to out.   MODE 1: red.v4 r into g_sums[batch[node]].
// ---------------------------------------------------------------------------
template <int MODE>
__global__ void __launch_bounds__(256) k_agg(const float* __restrict__ T_,
                                             float* __restrict__ out,
                                             const float* __restrict__ bias,
                                             const void* __restrict__ batch) {
    constexpr int F = HID;
    constexpr int C = F / 128;
    int gw = (blockIdx.x * 256 + threadIdx.x) >> 5;
    int lane = threadIdx.x & 31;
    if (gw >= N_NODES) return;
    int beg = __ldg(&g_rowptr[gw]);
    int end = __ldg(&g_rowptr[gw + 1]);
    float dd = __ldg(&g_dinv[gw]);

    const float4* Tv = (const float4*)T_;
    size_t rowq = (size_t)gw * (F / 4);

    float4 acc[C];
#pragma unroll
    for (int c = 0; c < C; c++) {
        float4 v = __ldg(&Tv[rowq + c * 32 + lane]);
        acc[c] = make_float4(v.x * dd, v.y * dd, v.z * dd, v.w * dd);
    }

    int j = beg;
    for (; j + 4 <= end; j += 4) {
        int2 e0 = __ldg(&g_csr[j + 0]);
        int2 e1 = __ldg(&g_csr[j + 1]);
        int2 e2 = __ldg(&g_csr[j + 2]);
        int2 e3 = __ldg(&g_csr[j + 3]);
        float n0 = __int_as_float(e0.y), n1 = __int_as_float(e1.y);
        float n2 = __int_as_float(e2.y), n3 = __int_as_float(e3.y);
#pragma unroll
        for (int c = 0; c < C; c++) {
            float4 v0 = __ldg(&Tv[(size_t)e0.x * (F / 4) + c * 32 + lane]);
            float4 v1 = __ldg(&Tv[(size_t)e1.x * (F / 4) + c * 32 + lane]);
            float4 v2 = __ldg(&Tv[(size_t)e2.x * (F / 4) + c * 32 + lane]);
            float4 v3 = __ldg(&Tv[(size_t)e3.x * (F / 4) + c * 32 + lane]);
            fma4(acc[c], v0, n0);
            fma4(acc[c], v1, n1);
            fma4(acc[c], v2, n2);
            fma4(acc[c], v3, n3);
        }
    }
    for (; j < end; j++) {
        int2 e = __ldg(&g_csr[j]);
        float n = __int_as_float(e.y);
#pragma unroll
        for (int c = 0; c < C; c++) {
            float4 v = __ldg(&Tv[(size_t)e.x * (F / 4) + c * 32 + lane]);
            fma4(acc[c], v, n);
        }
    }

#pragma unroll
    for (int c = 0; c < C; c++) {
        float4 b = __ldg((const float4*)(bias + c * 128 + lane * 4));
        acc[c].x = fmaxf(acc[c].x * dd + b.x, 0.f);
        acc[c].y = fmaxf(acc[c].y * dd + b.y, 0.f);
        acc[c].z = fmaxf(acc[c].z * dd + b.z, 0.f);
        acc[c].w = fmaxf(acc[c].w * dd + b.w, 0.f);
    }

    if (MODE == 0) {
#pragma unroll
        for (int c = 0; c < C; c++)
            ((float4*)out)[rowq + c * 32 + lane] = acc[c];
    } else {
        int g = idx_at(batch, gw, g_is64);
#pragma unroll
        for (int c = 0; c < C; c++)
            red_add_v4(g_sums + g * HID + c * 128 + lane * 4, acc[c]);
    }
}

// ---------------------------------------------------------------------------
// (9) Final: mean, FC, log_softmax
// ---------------------------------------------------------------------------
__global__ void k_final(const float* __restrict__ fcw, const float* __restrict__ fcb,
                        float* __restrict__ out) {
    int g = threadIdx.x;
    if (g >= N_GRAPHS) return;
    float inv = 1.0f / fmaxf(g_cnt[g], 1.0f);
    float l0 = fcb[0], l1 = fcb[1];
#pragma unroll 8
    for (int f = 0; f < HID; f++) {
        float p = g_sums[g * HID + f] * inv;
        l0 += p * fcw[f * N_CLS + 0];
        l1 += p * fcw[f * N_CLS + 1];
    }
    float m = fmaxf(l0, l1);
    float lse = m + logf(expf(l0 - m) + expf(l1 - m));
    out[g * N_CLS + 0] = l0 - lse;
    out[g * N_CLS + 1] = l1 - lse;
}

// ---------------------------------------------------------------------------
extern "C" void kernel_launch(void* const* d_in, const int* in_sizes, int n_in,
                              void* d_out, int out_size) {
    const float* x     = (const float*)d_in[0];
    const void*  edges = d_in[1];
    const void*  batch = d_in[2];
    const float* W1    = (const float*)d_in[3];
    const float* b1    = (const float*)d_in[4];
    const float* W2    = (const float*)d_in[5];
    const float* b2    = (const float*)d_in[6];
    const float* fcw   = (const float*)d_in[7];
    const float* fcb   = (const float*)d_in[8];
    float* out = (float*)d_out;

    const int T = 256;
    dim3 gemm_grid(HID / 64, (N_NODES + 127) / 128);
    unsigned agg_grid = (unsigned)(((long long)N_NODES * 32 + 255) / 256);

    k_zero<<<(N_NODES + T - 1) / T, T>>>(edges);                       // 1
    k_deg_cnt<<<(N_EDGES + T - 1) / T, T>>>(edges, batch);             // 2
    k_scan_rsqrt<<<1, 1024>>>();                                       // 3
    k_gemm<<<gemm_grid, 128>>>(x, W1, g_buf2, N_NODES, HID, F_IN);     // 4 <- profiled
    k_fill<<<(N_EDGES + T - 1) / T, T>>>(edges);                       // 5
    k_agg<0><<<agg_grid, 256>>>(g_buf2, g_buf1, b1, batch);            // 6
    k_gemm<<<gemm_grid, 128>>>(g_buf1, W2, g_buf2, N_NODES, HID, HID); // 7
    k_agg<1><<<agg_grid, 256>>>(g_buf2, nullptr, b2, batch);           // 8
    k_final<<<1, 64>>>(fcw, fcb, out);                                 // 9
}

// round 9
// speedup vs baseline: 31.3948x; 31.3948x over previous
#include <cuda_runtime.h>
#include <math.h>

#define N_NODES  100000
#define N_EDGES  3200000
#define N_GRAPHS 64
#define F_IN     128
#define HID      256
#define N_CLS    2

// ---------------------------------------------------------------------------
// Scratch. CRITICAL RULE: these symbols are referenced ONLY inside device
// code. They are NEVER passed as kernel arguments from kernel_launch — on
// GB300 (ATS/HMM) a host-side reference silently yields the host shadow.
// ---------------------------------------------------------------------------
__device__ __align__(16) float g_dinv9[N_NODES];
__device__ __align__(16) int   g_deg9[N_NODES];
__device__ __align__(16) int   g_rowptr9[N_NODES + 1];
__device__ __align__(16) int   g_cursor9[N_NODES];
__device__ __align__(16) int2  g_csr9[N_EDGES];                 // {src, dinv[src]}
__device__ __align__(16) float g_t1_9[(size_t)N_NODES * F_IN];  // A~ x
__device__ __align__(16) float g_h1_9[(size_t)N_NODES * HID];   // relu(t1 W1 + b1)
__device__ __align__(16) float g_t2_9[(size_t)N_NODES * HID];   // A~ h1
__device__ __align__(16) float g_h2_9[(size_t)N_NODES * HID];   // relu(t2 W2 + b2)
__device__ __align__(16) float g_sums9[N_GRAPHS * HID];
__device__ float g_cnt9[N_GRAPHS];
__device__ int   g_is649;

// ---------------------------------------------------------------------------
__device__ __forceinline__ void red_v4_9(float* p, float4 v) {
    asm volatile("red.global.add.v4.f32 [%0], {%1, %2, %3, %4};"
                 :: "l"(p), "f"(v.x), "f"(v.y), "f"(v.z), "f"(v.w) : "memory");
}
__device__ __forceinline__ int idx_9(const void* p, long long i, int is64) {
    return is64 ? (int)((const long long*)p)[i] : ((const int*)p)[i];
}
__device__ __forceinline__ void fma4_9(float4& a, float4 v, float w) {
    a.x += v.x * w; a.y += v.y * w; a.z += v.z * w; a.w += v.w * w;
}

// ---------------------------------------------------------------------------
// (1) zero counters/sums + detect index dtype
// ---------------------------------------------------------------------------
__global__ void k_prep9(const void* __restrict__ edges) {
    int i = blockIdx.x * blockDim.x + threadIdx.x;
    if (i < N_NODES) g_deg9[i] = 0;
    if (i < N_GRAPHS * HID) g_sums9[i] = 0.0f;
    if (i < N_GRAPHS) g_cnt9[i] = 0.0f;
    if (i == 0) {
        const long long* p = (const long long*)edges;
        int is64 = 1;
        for (int j = 0; j < 512; j++) {
            long long v = p[j];
            if (v < 0 || v >= N_NODES) { is64 = 0; break; }
        }
        g_is649 = is64;
    }
}

// (2) in-degree + per-graph node counts
__global__ void k_deg9(const void* __restrict__ edges, const void* __restrict__ batch) {
    int i = blockIdx.x * blockDim.x + threadIdx.x;
    int is64 = g_is649;
    if (i < N_EDGES) {
        int d = idx_9(edges, (long long)N_EDGES + i, is64);
        atomicAdd(&g_deg9[d], 1);
    }
    if (i < N_NODES) {
        int g = idx_9(batch, i, is64);
        atomicAdd(&g_cnt9[g], 1.0f);
    }
}

// (3) single-block scan -> rowptr/cursor; dinv = rsqrt(deg+1)
__global__ void k_scan9() {
    const int T = 1024;
    const int CH = (N_NODES + T - 1) / T;
    __shared__ int part[T];
    int t = threadIdx.x;
    int base = t * CH;
    int local = 0;
    for (int i = 0; i < CH; i++) {
        int idx = base + i;
        if (idx < N_NODES) local += g_deg9[idx];
    }
    part[t] = local;
    __syncthreads();
    for (int off = 1; off < T; off <<= 1) {
        int v = (t >= off) ? part[t - off] : 0;
        __syncthreads();
        if (t >= off) part[t] += v;
        __syncthreads();
    }
    int prefix = (t == 0) ? 0 : part[t - 1];
    for (int i = 0; i < CH; i++) {
        int idx = base + i;
        if (idx < N_NODES) {
            g_rowptr9[idx] = prefix;
            g_cursor9[idx] = prefix;
            prefix += g_deg9[idx];
        }
    }
    if (t == T - 1) g_rowptr9[N_NODES] = part[T - 1];
    __syncthreads();
    for (int i = t; i < N_NODES; i += T)
        g_dinv9[i] = rsqrtf((float)(g_deg9[i] + 1));
}

// (4) CSR fill {src, dinv[src]}
__global__ void k_fill9(const void* __restrict__ edges) {
    int e = blockIdx.x * blockDim.x + threadIdx.x;
    if (e >= N_EDGES) return;
    int is64 = g_is649;
    int s = idx_9(edges, e, is64);
    int d = idx_9(edges, (long long)N_EDGES + e, is64);
    int slot = atomicAdd(&g_cursor9[d], 1);
    g_csr9[slot] = make_int2(s, __float_as_int(g_dinv9[s]));
}

// ---------------------------------------------------------------------------
// (5) agg1: g_t1 = A~ x  (F=128; warp/node, lane owns one float4)
//     X is a genuine device pointer (harness d_in) — safe as argument.
// ---------------------------------------------------------------------------
__global__ void __launch_bounds__(256) k_agg1_9(const float* __restrict__ X) {
    int gw = (blockIdx.x * 256 + threadIdx.x) >> 5;
    int lane = threadIdx.x & 31;
    if (gw >= N_NODES) return;
    int beg = __ldg(&g_rowptr9[gw]);
    int end = __ldg(&g_rowptr9[gw + 1]);
    float dd = __ldg(&g_dinv9[gw]);

    const float4* Xv = (const float4*)X;
    float4 a0 = __ldg(&Xv[(size_t)gw * 32 + lane]);
    float4 acc = make_float4(a0.x * dd, a0.y * dd, a0.z * dd, a0.w * dd);

    int j = beg;
    for (; j + 8 <= end; j += 8) {
        float4 s = make_float4(0.f, 0.f, 0.f, 0.f);
#pragma unroll
        for (int u = 0; u < 8; u++) {
            int2 e = __ldg(&g_csr9[j + u]);
            float4 v = __ldg(&Xv[(size_t)e.x * 32 + lane]);
            fma4_9(s, v, __int_as_float(e.y));
        }
        acc.x += s.x; acc.y += s.y; acc.z += s.z; acc.w += s.w;
    }
    for (; j < end; j++) {
        int2 e = __ldg(&g_csr9[j]);
        float4 v = __ldg(&Xv[(size_t)e.x * 32 + lane]);
        fma4_9(acc, v, __int_as_float(e.y));
    }
    acc.x *= dd; acc.y *= dd; acc.z *= dd; acc.w *= dd;
    ((float4*)g_t1_9)[(size_t)gw * 32 + lane] = acc;   // internal symbol: device
}

// ---------------------------------------------------------------------------
// (7) agg2: g_t2 = A~ h1  (F=256; warp/node, lane owns two float4)
//     Reads g_h1_9 / writes g_t2_9 via internal symbols only.
// ---------------------------------------------------------------------------
__global__ void __launch_bounds__(256) k_agg2_9() {
    int gw = (blockIdx.x * 256 + threadIdx.x) >> 5;
    int lane = threadIdx.x & 31;
    if (gw >= N_NODES) return;
    int beg = __ldg(&g_rowptr9[gw]);
    int end = __ldg(&g_rowptr9[gw + 1]);
    float dd = __ldg(&g_dinv9[gw]);

    const float4* Hv = (const float4*)g_h1_9;
    float4 acc0, acc1;
    {
        float4 v0 = __ldg(&Hv[(size_t)gw * 64 + lane]);
        float4 v1 = __ldg(&Hv[(size_t)gw * 64 + 32 + lane]);
        acc0 = make_float4(v0.x * dd, v0.y * dd, v0.z * dd, v0.w * dd);
        acc1 = make_float4(v1.x * dd, v1.y * dd, v1.z * dd, v1.w * dd);
    }
    int j = beg;
    for (; j + 4 <= end; j += 4) {
#pragma unroll
        for (int u = 0; u < 4; u++) {
            int2 e = __ldg(&g_csr9[j + u]);
            float n = __int_as_float(e.y);
            float4 v0 = __ldg(&Hv[(size_t)e.x * 64 + lane]);
            float4 v1 = __ldg(&Hv[(size_t)e.x * 64 + 32 + lane]);
            fma4_9(acc0, v0, n);
            fma4_9(acc1, v1, n);
        }
    }
    for (; j < end; j++) {
        int2 e = __ldg(&g_csr9[j]);
        float n = __int_as_float(e.y);
        float4 v0 = __ldg(&Hv[(size_t)e.x * 64 + lane]);
        float4 v1 = __ldg(&Hv[(size_t)e.x * 64 + 32 + lane]);
        fma4_9(acc0, v0, n);
        fma4_9(acc1, v1, n);
    }
    acc0.x *= dd; acc0.y *= dd; acc0.z *= dd; acc0.w *= dd;
    acc1.x *= dd; acc1.y *= dd; acc1.z *= dd; acc1.w *= dd;
    ((float4*)g_t2_9)[(size_t)gw * 64 + lane] = acc0;
    ((float4*)g_t2_9)[(size_t)gw * 64 + 32 + lane] = acc1;
}

// ---------------------------------------------------------------------------
// (6,8) SGEMM + bias + ReLU (proven R2 structure: BM=128,BN=64,BK=16,
// 128 threads, 8x8/thread, transposed A-tile). A and C are selected INSIDE
// device code by LAYER — never passed from host.
//   LAYER 1: g_h1 = relu(g_t1 @ W1 + b1), K=128
//   LAYER 2: g_h2 = relu(g_t2 @ W2 + b2), K=256
// ---------------------------------------------------------------------------
template <int LAYER>
__global__ void __launch_bounds__(128) k_gemm9(const float* __restrict__ W,
                                               const float* __restrict__ bias) {
    constexpr int BM = 128, BN = 64, BK = 16, TM = 8, TN = 8;
    constexpr int K = (LAYER == 1) ? F_IN : HID;
    constexpr int N = HID;
    constexpr int M = N_NODES;
    const float* A = (LAYER == 1) ? g_t1_9 : g_t2_9;   // device-code symbol ref
    float*       C = (LAYER == 1) ? g_h1_9 : g_h2_9;

    __shared__ float Ast[BK][BM];
    __shared__ float Ws[BK][BN];

    const int tid = threadIdx.x;
    const int tx = tid % (BN / TN);
    const int ty = tid / (BN / TN);
    const int row0 = blockIdx.y * BM;
    const int col0 = blockIdx.x * BN;

    float acc[TM][TN];
#pragma unroll
    for (int i = 0; i < TM; i++)
#pragma unroll
        for (int j = 0; j < TN; j++) acc[i][j] = 0.0f;

    for (int k0 = 0; k0 < K; k0 += BK) {
#pragma unroll
        for (int it = 0; it < (BM * BK / 4) / 128; it++) {
            int j = tid + it * 128;
            int m = j / (BK / 4);
            int k4 = j % (BK / 4);
            int gm = row0 + m;
            float4 v = make_float4(0.f, 0.f, 0.f, 0.f);
            if (gm < M) v = *(const float4*)(A + (size_t)gm * K + k0 + k4 * 4);
            Ast[k4 * 4 + 0][m] = v.x;
            Ast[k4 * 4 + 1][m] = v.y;
            Ast[k4 * 4 + 2][m] = v.z;
            Ast[k4 * 4 + 3][m] = v.w;
        }
#pragma unroll
        for (int it = 0; it < (BK * BN / 4) / 128; it++) {
            int j = tid + it * 128;
            int k = j / (BN / 4);
            int n4 = j % (BN / 4);
            *(float4*)(&Ws[k][n4 * 4]) =
                *(const float4*)(W + (size_t)(k0 + k) * N + col0 + n4 * 4);
        }
        __syncthreads();
#pragma unroll
        for (int k = 0; k < BK; k++) {
            float4 a0 = *(const float4*)(&Ast[k][ty * TM]);
            float4 a1 = *(const float4*)(&Ast[k][ty * TM + 4]);
            float4 w0 = *(const float4*)(&Ws[k][tx * TN]);
            float4 w1 = *(const float4*)(&Ws[k][tx * TN + 4]);
            float av[TM] = {a0.x, a0.y, a0.z, a0.w, a1.x, a1.y, a1.z, a1.w};
            float wv[TN] = {w0.x, w0.y, w0.z, w0.w, w1.x, w1.y, w1.z, w1.w};
#pragma unroll
            for (int i = 0; i < TM; i++)
#pragma unroll
                for (int j = 0; j < TN; j++) acc[i][j] += av[i] * wv[j];
        }
        __syncthreads();
    }

#pragma unroll
    for (int i = 0; i < TM; i++) {
        int gm = row0 + ty * TM + i;
        if (gm >= M) continue;
#pragma unroll
        for (int j = 0; j < TN; j += 4) {
            int gn = col0 + tx * TN + j;
            float4 v;
            v.x = fmaxf(acc[i][j + 0] + bias[gn + 0], 0.f);
            v.y = fmaxf(acc[i][j + 1] + bias[gn + 1], 0.f);
            v.z = fmaxf(acc[i][j + 2] + bias[gn + 2], 0.f);
            v.w = fmaxf(acc[i][j + 3] + bias[gn + 3], 0.f);
            *(float4*)(C + (size_t)gm * N + gn) = v;
        }
    }
}

// ---------------------------------------------------------------------------
// (9) Pool: g_sums[batch[node]] += h2[node]   (h2/sums internal)
// ---------------------------------------------------------------------------
__global__ void k_pool9(const void* __restrict__ batch) {
    size_t i = (size_t)blockIdx.x * blockDim.x + threadIdx.x;
    if (i >= (size_t)N_NODES * (HID / 4)) return;
    int node = (int)(i >> 6);
    int f4 = (int)(i & 63);
    int g = idx_9(batch, node, g_is649);
    float4 v = ((const float4*)g_h2_9)[(size_t)node * (HID / 4) + f4];
    red_v4_9(g_sums9 + g * HID + f4 * 4, v);
}

// (10) Final: mean, FC, log_softmax
__global__ void k_final9(const float* __restrict__ fcw, const float* __restrict__ fcb,
                         float* __restrict__ out) {
    int g = threadIdx.x;
    if (g >= N_GRAPHS) return;
    float inv = 1.0f / fmaxf(g_cnt9[g], 1.0f);
    float l0 = fcb[0], l1 = fcb[1];
#pragma unroll 8
    for (int f = 0; f < HID; f++) {
        float p = g_sums9[g * HID + f] * inv;
        l0 += p * fcw[f * N_CLS + 0];
        l1 += p * fcw[f * N_CLS + 1];
    }
    float m = fmaxf(l0, l1);
    float lse = m + logf(expf(l0 - m) + expf(l1 - m));
    out[g * N_CLS + 0] = l0 - lse;
    out[g * N_CLS + 1] = l1 - lse;
}

// ---------------------------------------------------------------------------
// Launch: ONLY genuine device pointers (d_in/d_out) cross the host boundary.
// ---------------------------------------------------------------------------
extern "C" void kernel_launch(void* const* d_in, const int* in_sizes, int n_in,
                              void* d_out, int out_size) {
    const float* x     = (const float*)d_in[0];
    const void*  edges = d_in[1];
    const void*  batch = d_in[2];
    const float* W1    = (const float*)d_in[3];
    const float* b1    = (const float*)d_in[4];
    const float* W2    = (const float*)d_in[5];
    const float* b2    = (const float*)d_in[6];
    const float* fcw   = (const float*)d_in[7];
    const float* fcb   = (const float*)d_in[8];
    float* out = (float*)d_out;

    const int T = 256;
    dim3 gemm_grid(HID / 64, (N_NODES + 127) / 128);
    unsigned warps_grid = (unsigned)(((long long)N_NODES * 32 + 255) / 256);
    unsigned pool_grid  = (unsigned)(((long long)N_NODES * (HID / 4) + T - 1) / T);

    k_prep9<<<(N_NODES + T - 1) / T, T>>>(edges);               // 1
    k_deg9<<<(N_EDGES + T - 1) / T, T>>>(edges, batch);         // 2
    k_scan9<<<1, 1024>>>();                                     // 3
    k_fill9<<<(N_EDGES + T - 1) / T, T>>>(edges);               // 4
    k_agg1_9<<<warps_grid, 256>>>(x);                           // 5
    k_gemm9<1><<<gemm_grid, 128>>>(W1, b1);                     // 6
    k_agg2_9<<<warps_grid, 256>>>();                            // 7
    k_gemm9<2><<<gemm_grid, 128>>>(W2, b2);                     // 8
    k_pool9<<<pool_grid, T>>>(batch);                           // 9
    k_final9<<<1, 64>>>(fcw, fcb, out);                         // 10
}

// round 11
// speedup vs baseline: 35.4911x; 1.1305x over previous
#include <cuda_runtime.h>
#include <cstdint>
#include <math.h>

#define N_NODES  100000
#define N_EDGES  3200000
#define N_GRAPHS 64
#define F_IN     128
#define HID      256
#define N_CLS    2

// ---------------------------------------------------------------------------
// Scratch — referenced ONLY from device code (never passed as kernel args:
// on GB300 ATS a host-side symbol reference yields the host shadow).
// ---------------------------------------------------------------------------
__device__ __align__(16) float g_dinv9[N_NODES];
__device__ __align__(16) int   g_deg9[N_NODES];
__device__ __align__(16) int   g_rowptr9[N_NODES + 1];
__device__ __align__(16) int   g_cursor9[N_NODES];
__device__ __align__(16) int2  g_csr9[N_EDGES];                 // {src, dinv[src]}
__device__ __align__(16) float g_t1_9[(size_t)N_NODES * F_IN];  // A~ x
__device__ __align__(16) float g_h1_9[(size_t)N_NODES * HID];   // relu(t1 W1 + b1)
__device__ __align__(16) float g_t2_9[(size_t)N_NODES * HID];   // A~ h1
__device__ __align__(16) float g_h2_9[(size_t)N_NODES * HID];   // relu(t2 W2 + b2)
__device__ __align__(16) float g_sums9[N_GRAPHS * HID];
__device__ float g_cnt9[N_GRAPHS];
__device__ int   g_is649;

// ---------------------------------------------------------------------------
__device__ __forceinline__ void red_v4_9(float* p, float4 v) {
    asm volatile("red.global.add.v4.f32 [%0], {%1, %2, %3, %4};"
                 :: "l"(p), "f"(v.x), "f"(v.y), "f"(v.z), "f"(v.w) : "memory");
}
__device__ __forceinline__ int idx_9(const void* p, long long i, int is64) {
    return is64 ? (int)((const long long*)p)[i] : ((const int*)p)[i];
}
__device__ __forceinline__ void fma4_9(float4& a, float4 v, float w) {
    a.x += v.x * w; a.y += v.y * w; a.z += v.z * w; a.w += v.w * w;
}
__device__ __forceinline__ uint32_t f2tf32(float a) {
    uint32_t r;
    asm("cvt.rna.tf32.f32 %0, %1;" : "=r"(r) : "f"(a));
    return r;
}
__device__ __forceinline__ void mma_tf32(float c[4], const uint32_t a[4],
                                         const uint32_t b[2]) {
    asm volatile(
        "mma.sync.aligned.m16n8k8.row.col.f32.tf32.tf32.f32 "
        "{%0,%1,%2,%3}, {%4,%5,%6,%7}, {%8,%9}, {%0,%1,%2,%3};"
        : "+f"(c[0]), "+f"(c[1]), "+f"(c[2]), "+f"(c[3])
        : "r"(a[0]), "r"(a[1]), "r"(a[2]), "r"(a[3]), "r"(b[0]), "r"(b[1]));
}
__device__ __forceinline__ void cp_async16(void* smem_dst, const void* gsrc) {
    uint32_t d = (uint32_t)__cvta_generic_to_shared(smem_dst);
    asm volatile("cp.async.cg.shared.global [%0], [%1], 16;" :: "r"(d), "l"(gsrc));
}

// ---------------------------------------------------------------------------
// (1) zero counters/sums + detect index dtype
// ---------------------------------------------------------------------------
__global__ void k_prep9(const void* __restrict__ edges) {
    int i = blockIdx.x * blockDim.x + threadIdx.x;
    if (i < N_NODES) g_deg9[i] = 0;
    if (i < N_GRAPHS * HID) g_sums9[i] = 0.0f;
    if (i < N_GRAPHS) g_cnt9[i] = 0.0f;
    if (i == 0) {
        const long long* p = (const long long*)edges;
        int is64 = 1;
        for (int j = 0; j < 512; j++) {
            long long v = p[j];
            if (v < 0 || v >= N_NODES) { is64 = 0; break; }
        }
        g_is649 = is64;
    }
}

// (2) in-degree + per-graph node counts
__global__ void k_deg9(const void* __restrict__ edges, const void* __restrict__ batch) {
    int i = blockIdx.x * blockDim.x + threadIdx.x;
    int is64 = g_is649;
    if (i < N_EDGES) {
        int d = idx_9(edges, (long long)N_EDGES + i, is64);
        atomicAdd(&g_deg9[d], 1);
    }
    if (i < N_NODES) {
        int g = idx_9(batch, i, is64);
        atomicAdd(&g_cnt9[g], 1.0f);
    }
}

// (3) single-block scan -> rowptr/cursor; dinv = rsqrt(deg+1)
__global__ void k_scan9() {
    const int T = 1024;
    const int CH = (N_NODES + T - 1) / T;
    __shared__ int part[T];
    int t = threadIdx.x;
    int base = t * CH;
    int local = 0;
    for (int i = 0; i < CH; i++) {
        int idx = base + i;
        if (idx < N_NODES) local += g_deg9[idx];
    }
    part[t] = local;
    __syncthreads();
    for (int off = 1; off < T; off <<= 1) {
        int v = (t >= off) ? part[t - off] : 0;
        __syncthreads();
        if (t >= off) part[t] += v;
        __syncthreads();
    }
    int prefix = (t == 0) ? 0 : part[t - 1];
    for (int i = 0; i < CH; i++) {
        int idx = base + i;
        if (idx < N_NODES) {
            g_rowptr9[idx] = prefix;
            g_cursor9[idx] = prefix;
            prefix += g_deg9[idx];
        }
    }
    if (t == T - 1) g_rowptr9[N_NODES] = part[T - 1];
    __syncthreads();
    for (int i = t; i < N_NODES; i += T)
        g_dinv9[i] = rsqrtf((float)(g_deg9[i] + 1));
}

// (4) CSR fill {src, dinv[src]}
__global__ void k_fill9(const void* __restrict__ edges) {
    int e = blockIdx.x * blockDim.x + threadIdx.x;
    if (e >= N_EDGES) return;
    int is64 = g_is649;
    int s = idx_9(edges, e, is64);
    int d = idx_9(edges, (long long)N_EDGES + e, is64);
    int slot = atomicAdd(&g_cursor9[d], 1);
    g_csr9[slot] = make_int2(s, __float_as_int(g_dinv9[s]));
}

// ---------------------------------------------------------------------------
// (5) agg1: g_t1 = A~ x  (F=128; warp/node)
// ---------------------------------------------------------------------------
__global__ void __launch_bounds__(256) k_agg1_9(const float* __restrict__ X) {
    int gw = (blockIdx.x * 256 + threadIdx.x) >> 5;
    int lane = threadIdx.x & 31;
    if (gw >= N_NODES) return;
    int beg = __ldg(&g_rowptr9[gw]);
    int end = __ldg(&g_rowptr9[gw + 1]);
    float dd = __ldg(&g_dinv9[gw]);

    const float4* Xv = (const float4*)X;
    float4 a0 = __ldg(&Xv[(size_t)gw * 32 + lane]);
    float4 acc = make_float4(a0.x * dd, a0.y * dd, a0.z * dd, a0.w * dd);

    int j = beg;
    for (; j + 8 <= end; j += 8) {
        float4 s = make_float4(0.f, 0.f, 0.f, 0.f);
#pragma unroll
        for (int u = 0; u < 8; u++) {
            int2 e = __ldg(&g_csr9[j + u]);
            float4 v = __ldg(&Xv[(size_t)e.x * 32 + lane]);
            fma4_9(s, v, __int_as_float(e.y));
        }
        acc.x += s.x; acc.y += s.y; acc.z += s.z; acc.w += s.w;
    }
    for (; j < end; j++) {
        int2 e = __ldg(&g_csr9[j]);
        float4 v = __ldg(&Xv[(size_t)e.x * 32 + lane]);
        fma4_9(acc, v, __int_as_float(e.y));
    }
    acc.x *= dd; acc.y *= dd; acc.z *= dd; acc.w *= dd;
    ((float4*)g_t1_9)[(size_t)gw * 32 + lane] = acc;
}

// ---------------------------------------------------------------------------
// (7) agg2: g_t2 = A~ h1  (F=256; warp/node)
// ---------------------------------------------------------------------------
__global__ void __launch_bounds__(256) k_agg2_9() {
    int gw = (blockIdx.x * 256 + threadIdx.x) >> 5;
    int lane = threadIdx.x & 31;
    if (gw >= N_NODES) return;
    int beg = __ldg(&g_rowptr9[gw]);
    int end = __ldg(&g_rowptr9[gw + 1]);
    float dd = __ldg(&g_dinv9[gw]);

    const float4* Hv = (const float4*)g_h1_9;
    float4 acc0, acc1;
    {
        float4 v0 = __ldg(&Hv[(size_t)gw * 64 + lane]);
        float4 v1 = __ldg(&Hv[(size_t)gw * 64 + 32 + lane]);
        acc0 = make_float4(v0.x * dd, v0.y * dd, v0.z * dd, v0.w * dd);
        acc1 = make_float4(v1.x * dd, v1.y * dd, v1.z * dd, v1.w * dd);
    }
    int j = beg;
    for (; j + 4 <= end; j += 4) {
#pragma unroll
        for (int u = 0; u < 4; u++) {
            int2 e = __ldg(&g_csr9[j + u]);
            float n = __int_as_float(e.y);
            float4 v0 = __ldg(&Hv[(size_t)e.x * 64 + lane]);
            float4 v1 = __ldg(&Hv[(size_t)e.x * 64 + 32 + lane]);
            fma4_9(acc0, v0, n);
            fma4_9(acc1, v1, n);
        }
    }
    for (; j < end; j++) {
        int2 e = __ldg(&g_csr9[j]);
        float n = __int_as_float(e.y);
        float4 v0 = __ldg(&Hv[(size_t)e.x * 64 + lane]);
        float4 v1 = __ldg(&Hv[(size_t)e.x * 64 + 32 + lane]);
        fma4_9(acc0, v0, n);
        fma4_9(acc1, v1, n);
    }
    acc0.x *= dd; acc0.y *= dd; acc0.z *= dd; acc0.w *= dd;
    acc1.x *= dd; acc1.y *= dd; acc1.z *= dd; acc1.w *= dd;
    ((float4*)g_t2_9)[(size_t)gw * 64 + lane] = acc0;
    ((float4*)g_t2_9)[(size_t)gw * 64 + 32 + lane] = acc1;
}

// ---------------------------------------------------------------------------
// (6,8) Tensor-core GEMM: 3xTF32 mma.sync (hi*hi + lo*hi + hi*lo ≈ fp32).
// BM=128 BN=128 BK=16, 256 threads = 8 warps (4M x 2N), warp tile 32x64.
// cp.async double-buffered smem. Fused bias + ReLU epilogue.
//   LAYER 1: g_h1 = relu(g_t1 @ W1 + b1), K=128
//   LAYER 2: g_h2 = relu(g_t2 @ W2 + b2), K=256
// ---------------------------------------------------------------------------
template <int LAYER>
__global__ void __launch_bounds__(256) k_gemm_mma9(const float* __restrict__ W,
                                                   const float* __restrict__ bias) {
    constexpr int K = (LAYER == 1) ? F_IN : HID;
    constexpr int BM = 128, BN = 128, BK = 16;
    constexpr int NT = K / BK;
    constexpr int ASTR = BK + 4;    // 20: bank-conflict-free frag reads
    constexpr int BSTR = BN + 8;    // 136: conflict-free frag reads
    const float* A = (LAYER == 1) ? g_t1_9 : g_t2_9;
    float*       C = (LAYER == 1) ? g_h1_9 : g_h2_9;

    __shared__ float As[2][BM][ASTR];
    __shared__ float Bs[2][BK][BSTR];

    const int tid = threadIdx.x;
    const int wid = tid >> 5, lane = tid & 31;
    const int warpM = wid >> 1, warpN = wid & 1;
    const int row0 = blockIdx.y * BM, col0 = blockIdx.x * BN;
    const int gid = lane >> 2, tig = lane & 3;

    float c[2][8][4];
#pragma unroll
    for (int mt = 0; mt < 2; mt++)
#pragma unroll
        for (int nt = 0; nt < 8; nt++)
#pragma unroll
            for (int q = 0; q < 4; q++) c[mt][nt][q] = 0.0f;

    auto load_tile = [&](int buf, int k0) {
#pragma unroll
        for (int i = 0; i < 2; i++) {   // A: 128x16 = 512 float4
            int idx = tid + i * 256;
            int m = idx >> 2, k4 = idx & 3;
            int gm = min(row0 + m, N_NODES - 1);   // clamp; invalid rows dropped in epi
            cp_async16(&As[buf][m][k4 * 4], A + (size_t)gm * K + k0 + k4 * 4);
        }
#pragma unroll
        for (int i = 0; i < 2; i++) {   // B: 16x128 = 512 float4
            int idx = tid + i * 256;
            int k = idx >> 5, n4 = idx & 31;
            cp_async16(&Bs[buf][k][n4 * 4], W + (size_t)(k0 + k) * HID + col0 + n4 * 4);
        }
        asm volatile("cp.async.commit_group;");
    };

    auto compute = [&](int buf) {
#pragma unroll
        for (int ks = 0; ks < 2; ks++) {
            const int k0 = ks * 8;
            uint32_t ahi[2][4], alo[2][4];
#pragma unroll
            for (int mt = 0; mt < 2; mt++) {
                int m = warpM * 32 + mt * 16;
                float a[4];
                a[0] = As[buf][m + gid][k0 + tig];
                a[1] = As[buf][m + gid + 8][k0 + tig];
                a[2] = As[buf][m + gid][k0 + tig + 4];
                a[3] = As[buf][m + gid + 8][k0 + tig + 4];
#pragma unroll
                for (int q = 0; q < 4; q++) {
                    ahi[mt][q] = f2tf32(a[q]);
                    alo[mt][q] = f2tf32(a[q] - __uint_as_float(ahi[mt][q]));
                }
            }
            uint32_t bhi[8][2], blo[8][2];
#pragma unroll
            for (int nt = 0; nt < 8; nt++) {
                int n = warpN * 64 + nt * 8 + gid;
                float b0 = Bs[buf][k0 + tig][n];
                float b1 = Bs[buf][k0 + tig + 4][n];
                bhi[nt][0] = f2tf32(b0);
                blo[nt][0] = f2tf32(b0 - __uint_as_float(bhi[nt][0]));
                bhi[nt][1] = f2tf32(b1);
                blo[nt][1] = f2tf32(b1 - __uint_as_float(bhi[nt][1]));
            }
#pragma unroll
            for (int mt = 0; mt < 2; mt++)
#pragma unroll
                for (int nt = 0; nt < 8; nt++) {
                    mma_tf32(c[mt][nt], alo[mt], bhi[nt]);
                    mma_tf32(c[mt][nt], ahi[mt], blo[nt]);
                    mma_tf32(c[mt][nt], ahi[mt], bhi[nt]);
                }
        }
    };

    load_tile(0, 0);
    for (int t = 0; t < NT; t++) {
        if (t + 1 < NT) {
            load_tile((t + 1) & 1, (t + 1) * BK);
            asm volatile("cp.async.wait_group 1;");
        } else {
            asm volatile("cp.async.wait_group 0;");
        }
        __syncthreads();
        compute(t & 1);
        __syncthreads();
    }

    // Epilogue: bias + ReLU, float2 stores (c0,c1)/(c2,c3) per fragment
#pragma unroll
    for (int mt = 0; mt < 2; mt++) {
#pragma unroll
        for (int nt = 0; nt < 8; nt++) {
            int gn = col0 + warpN * 64 + nt * 8 + tig * 2;
            float b0 = __ldg(bias + gn), b1 = __ldg(bias + gn + 1);
            int r0 = row0 + warpM * 32 + mt * 16 + gid;
            int r1 = r0 + 8;
            if (r0 < N_NODES) {
                float2 v;
                v.x = fmaxf(c[mt][nt][0] + b0, 0.f);
                v.y = fmaxf(c[mt][nt][1] + b1, 0.f);
                *(float2*)(C + (size_t)r0 * HID + gn) = v;
            }
            if (r1 < N_NODES) {
                float2 v;
                v.x = fmaxf(c[mt][nt][2] + b0, 0.f);
                v.y = fmaxf(c[mt][nt][3] + b1, 0.f);
                *(float2*)(C + (size_t)r1 * HID + gn) = v;
            }
        }
    }
}

// ---------------------------------------------------------------------------
// (9) Pool: g_sums[batch[node]] += h2[node]
// ---------------------------------------------------------------------------
__global__ void k_pool9(const void* __restrict__ batch) {
    size_t i = (size_t)blockIdx.x * blockDim.x + threadIdx.x;
    if (i >= (size_t)N_NODES * (HID / 4)) return;
    int node = (int)(i >> 6);
    int f4 = (int)(i & 63);
    int g = idx_9(batch, node, g_is649);
    float4 v = ((const float4*)g_h2_9)[(size_t)node * (HID / 4) + f4];
    red_v4_9(g_sums9 + g * HID + f4 * 4, v);
}

// (10) Final: mean, FC, log_softmax
__global__ void k_final9(const float* __restrict__ fcw, const float* __restrict__ fcb,
                         float* __restrict__ out) {
    int g = threadIdx.x;
    if (g >= N_GRAPHS) return;
    float inv = 1.0f / fmaxf(g_cnt9[g], 1.0f);
    float l0 = fcb[0], l1 = fcb[1];
#pragma unroll 8
    for (int f = 0; f < HID; f++) {
        float p = g_sums9[g * HID + f] * inv;
        l0 += p * fcw[f * N_CLS + 0];
        l1 += p * fcw[f * N_CLS + 1];
    }
    float m = fmaxf(l0, l1);
    float lse = m + logf(expf(l0 - m) + expf(l1 - m));
    out[g * N_CLS + 0] = l0 - lse;
    out[g * N_CLS + 1] = l1 - lse;
}

// ---------------------------------------------------------------------------
extern "C" void kernel_launch(void* const* d_in, const int* in_sizes, int n_in,
                              void* d_out, int out_size) {
    const float* x     = (const float*)d_in[0];
    const void*  edges = d_in[1];
    const void*  batch = d_in[2];
    const float* W1    = (const float*)d_in[3];
    const float* b1    = (const float*)d_in[4];
    const float* W2    = (const float*)d_in[5];
    const float* b2    = (const float*)d_in[6];
    const float* fcw   = (const float*)d_in[7];
    const float* fcb   = (const float*)d_in[8];
    float* out = (float*)d_out;

    const int T = 256;
    dim3 gemm_grid(HID / 128, (N_NODES + 127) / 128);
    unsigned warps_grid = (unsigned)(((long long)N_NODES * 32 + 255) / 256);
    unsigned pool_grid  = (unsigned)(((long long)N_NODES * (HID / 4) + T - 1) / T);

    k_prep9<<<(N_NODES + T - 1) / T, T>>>(edges);               // 1
    k_deg9<<<(N_EDGES + T - 1) / T, T>>>(edges, batch);         // 2
    k_scan9<<<1, 1024>>>();                                     // 3
    k_fill9<<<(N_EDGES + T - 1) / T, T>>>(edges);               // 4
    k_agg1_9<<<warps_grid, 256>>>(x);                           // 5
    k_gemm_mma9<1><<<gemm_grid, 256>>>(W1, b1);                 // 6
    k_agg2_9<<<warps_grid, 256>>>();                            // 7
    k_gemm_mma9<2><<<gemm_grid, 256>>>(W2, b2);                 // 8
    k_pool9<<<pool_grid, T>>>(batch);                           // 9
    k_final9<<<1, 64>>>(fcw, fcb, out);                         // 10
}

// round 12
// speedup vs baseline: 40.4967x; 1.1410x over previous
#include <cuda_runtime.h>
#include <cuda_fp16.h>
#include <cstdint>
#include <math.h>

#define N_NODES  100000
#define N_EDGES  3200000
#define N_GRAPHS 64
#define F_IN     128
#define HID      256
#define N_CLS    2

// ---------------------------------------------------------------------------
// Scratch — referenced ONLY from device code (GB300 ATS: host-side symbol
// references yield the host shadow; never pass these as kernel args).
// Zero-invariants: g_deg re-zeroed by k_fill; g_sums/g_cnt by k_final.
// ---------------------------------------------------------------------------
__device__ __align__(16) float  g_dinv12[N_NODES];
__device__ __align__(16) int    g_deg12[N_NODES];
__device__ __align__(16) int    g_rowptr12[N_NODES + 1];
__device__ __align__(16) int    g_cursor12[N_NODES];
__device__ __align__(16) int2   g_csr12[N_EDGES];                  // {src, dinv[src]}
__device__ __align__(16) __half g_x16[(size_t)N_NODES * F_IN];     // x in fp16 (26MB)
__device__ __align__(16) float  g_t1_12[(size_t)N_NODES * F_IN];   // A~ x
__device__ __align__(16) __half g_h1_16[(size_t)N_NODES * HID];    // relu(t1 W1 + b1), fp16 (51MB)
__device__ __align__(16) float  g_t2_12[(size_t)N_NODES * HID];    // A~ h1
__device__ __align__(16) float  g_h2_12[(size_t)N_NODES * HID];    // relu(t2 W2 + b2)
__device__ __align__(16) float  g_sums12[N_GRAPHS * HID];
__device__ float g_cnt12[N_GRAPHS];
__device__ int   g_is6412;

// ---------------------------------------------------------------------------
__device__ __forceinline__ void red_v4_12(float* p, float4 v) {
    asm volatile("red.global.add.v4.f32 [%0], {%1, %2, %3, %4};"
                 :: "l"(p), "f"(v.x), "f"(v.y), "f"(v.z), "f"(v.w) : "memory");
}
__device__ __forceinline__ int idx_12(const void* p, long long i, int is64) {
    return is64 ? (int)((const long long*)p)[i] : ((const int*)p)[i];
}
__device__ __forceinline__ uint32_t f2tf32(float a) {
    uint32_t r;
    asm("cvt.rna.tf32.f32 %0, %1;" : "=r"(r) : "f"(a));
    return r;
}
__device__ __forceinline__ void mma_tf32(float c[4], const uint32_t a[4],
                                         const uint32_t b[2]) {
    asm volatile(
        "mma.sync.aligned.m16n8k8.row.col.f32.tf32.tf32.f32 "
        "{%0,%1,%2,%3}, {%4,%5,%6,%7}, {%8,%9}, {%0,%1,%2,%3};"
        : "+f"(c[0]), "+f"(c[1]), "+f"(c[2]), "+f"(c[3])
        : "r"(a[0]), "r"(a[1]), "r"(a[2]), "r"(a[3]), "r"(b[0]), "r"(b[1]));
}
__device__ __forceinline__ void cp_async16(void* smem_dst, const void* gsrc) {
    uint32_t d = (uint32_t)__cvta_generic_to_shared(smem_dst);
    asm volatile("cp.async.cg.shared.global [%0], [%1], 16;" :: "r"(d), "l"(gsrc));
}
__device__ __forceinline__ int detect64_12(const void* edges) {
    const long long* p = (const long long*)edges;
    int ok = 1;
#pragma unroll
    for (int j = 0; j < 32; j++) {
        long long v = p[j];
        if (v < 0 || v >= N_NODES) ok = 0;
    }
    return ok;
}

// ---------------------------------------------------------------------------
// (1) degree count + per-graph counts + x->fp16 conversion + dtype detect.
//     g_deg is zero on entry (static init first call; k_fill re-zeros after).
// ---------------------------------------------------------------------------
__global__ void k_deg12(const void* __restrict__ edges,
                        const void* __restrict__ batch,
                        const float* __restrict__ X) {
    __shared__ int s_is64;
    if (threadIdx.x == 0) {
        int v = detect64_12(edges);
        s_is64 = v;
        if (blockIdx.x == 0) g_is6412 = v;
    }
    __syncthreads();
    int is64 = s_is64;
    int i = blockIdx.x * blockDim.x + threadIdx.x;
    // x fp16 conversion: exactly N_NODES*32 = 3.2M float4s
    if (i < N_NODES * (F_IN / 4)) {
        float4 v = ((const float4*)X)[i];
        __half2 h0 = __floats2half2_rn(v.x, v.y);
        __half2 h1 = __floats2half2_rn(v.z, v.w);
        ((__half2*)g_x16)[i * 2 + 0] = h0;
        ((__half2*)g_x16)[i * 2 + 1] = h1;
    }
    if (i < N_EDGES) {
        int d = idx_12(edges, (long long)N_EDGES + i, is64);
        atomicAdd(&g_deg12[d], 1);
    }
    if (i < N_NODES) {
        int g = idx_12(batch, i, is64);
        atomicAdd(&g_cnt12[g], 1.0f);
    }
}

// (2) single-block scan -> rowptr/cursor; dinv = rsqrt(deg+1)
__global__ void k_scan12() {
    const int T = 1024;
    const int CH = (N_NODES + T - 1) / T;
    __shared__ int part[T];
    int t = threadIdx.x;
    int base = t * CH;
    int local = 0;
    for (int i = 0; i < CH; i++) {
        int idx = base + i;
        if (idx < N_NODES) local += g_deg12[idx];
    }
    part[t] = local;
    __syncthreads();
    for (int off = 1; off < T; off <<= 1) {
        int v = (t >= off) ? part[t - off] : 0;
        __syncthreads();
        if (t >= off) part[t] += v;
        __syncthreads();
    }
    int prefix = (t == 0) ? 0 : part[t - 1];
    for (int i = 0; i < CH; i++) {
        int idx = base + i;
        if (idx < N_NODES) {
            g_rowptr12[idx] = prefix;
            g_cursor12[idx] = prefix;
            prefix += g_deg12[idx];
        }
    }
    if (t == T - 1) g_rowptr12[N_NODES] = part[T - 1];
    __syncthreads();
    for (int i = t; i < N_NODES; i += T)
        g_dinv12[i] = rsqrtf((float)(g_deg12[i] + 1));
}

// (3) CSR fill {src, dinv[src]}; re-zeros g_deg for next replay
__global__ void k_fill12(const void* __restrict__ edges) {
    int e = blockIdx.x * blockDim.x + threadIdx.x;
    if (e < N_NODES) g_deg12[e] = 0;
    if (e >= N_EDGES) return;
    int is64 = g_is6412;
    int s = idx_12(edges, e, is64);
    int d = idx_12(edges, (long long)N_EDGES + e, is64);
    int slot = atomicAdd(&g_cursor12[d], 1);
    g_csr12[slot] = make_int2(s, __float_as_int(g_dinv12[s]));
}

// ---------------------------------------------------------------------------
// (4) agg1: g_t1 = A~ x   (F=128 fp16 gather; warp/node, lane owns 4 cols)
// ---------------------------------------------------------------------------
__global__ void __launch_bounds__(256) k_agg1_12() {
    int gw = (blockIdx.x * 256 + threadIdx.x) >> 5;
    int lane = threadIdx.x & 31;
    if (gw >= N_NODES) return;
    int beg = __ldg(&g_rowptr12[gw]);
    int end = __ldg(&g_rowptr12[gw + 1]);
    float dd = __ldg(&g_dinv12[gw]);

    const uint2* Xh = (const uint2*)g_x16;   // 8B = 4 halves per lane
    float4 acc;
    {
        uint2 u = __ldg(&Xh[(size_t)gw * 32 + lane]);
        float2 f0 = __half22float2(*(const __half2*)&u.x);
        float2 f1 = __half22float2(*(const __half2*)&u.y);
        acc = make_float4(f0.x * dd, f0.y * dd, f1.x * dd, f1.y * dd);
    }
    int j = beg;
    for (; j + 8 <= end; j += 8) {
#pragma unroll
        for (int u8 = 0; u8 < 8; u8++) {
            int2 e = __ldg(&g_csr12[j + u8]);
            float n = __int_as_float(e.y);
            uint2 u = __ldg(&Xh[(size_t)e.x * 32 + lane]);
            float2 f0 = __half22float2(*(const __half2*)&u.x);
            float2 f1 = __half22float2(*(const __half2*)&u.y);
            acc.x += f0.x * n; acc.y += f0.y * n;
            acc.z += f1.x * n; acc.w += f1.y * n;
        }
    }
    for (; j < end; j++) {
        int2 e = __ldg(&g_csr12[j]);
        float n = __int_as_float(e.y);
        uint2 u = __ldg(&Xh[(size_t)e.x * 32 + lane]);
        float2 f0 = __half22float2(*(const __half2*)&u.x);
        float2 f1 = __half22float2(*(const __half2*)&u.y);
        acc.x += f0.x * n; acc.y += f0.y * n;
        acc.z += f1.x * n; acc.w += f1.y * n;
    }
    acc.x *= dd; acc.y *= dd; acc.z *= dd; acc.w *= dd;
    ((float4*)g_t1_12)[(size_t)gw * 32 + lane] = acc;   // col lane*4
}

// ---------------------------------------------------------------------------
// (6) agg2: g_t2 = A~ h1   (F=256 fp16 gather; warp/node, lane owns 8 cols)
// ---------------------------------------------------------------------------
__global__ void __launch_bounds__(256) k_agg2_12() {
    int gw = (blockIdx.x * 256 + threadIdx.x) >> 5;
    int lane = threadIdx.x & 31;
    if (gw >= N_NODES) return;
    int beg = __ldg(&g_rowptr12[gw]);
    int end = __ldg(&g_rowptr12[gw + 1]);
    float dd = __ldg(&g_dinv12[gw]);

    const uint4* Hh = (const uint4*)g_h1_16;   // 16B = 8 halves per lane
    float acc[8];
    {
        uint4 u = __ldg(&Hh[(size_t)gw * 32 + lane]);
        const __half2* h = (const __half2*)&u;
#pragma unroll
        for (int q = 0; q < 4; q++) {
            float2 f = __half22float2(h[q]);
            acc[q * 2 + 0] = f.x * dd;
            acc[q * 2 + 1] = f.y * dd;
        }
    }
    int j = beg;
    for (; j + 4 <= end; j += 4) {
#pragma unroll
        for (int u4 = 0; u4 < 4; u4++) {
            int2 e = __ldg(&g_csr12[j + u4]);
            float n = __int_as_float(e.y);
            uint4 u = __ldg(&Hh[(size_t)e.x * 32 + lane]);
            const __half2* h = (const __half2*)&u;
#pragma unroll
            for (int q = 0; q < 4; q++) {
                float2 f = __half22float2(h[q]);
                acc[q * 2 + 0] += f.x * n;
                acc[q * 2 + 1] += f.y * n;
            }
        }
    }
    for (; j < end; j++) {
        int2 e = __ldg(&g_csr12[j]);
        float n = __int_as_float(e.y);
        uint4 u = __ldg(&Hh[(size_t)e.x * 32 + lane]);
        const __half2* h = (const __half2*)&u;
#pragma unroll
        for (int q = 0; q < 4; q++) {
            float2 f = __half22float2(h[q]);
            acc[q * 2 + 0] += f.x * n;
            acc[q * 2 + 1] += f.y * n;
        }
    }
    float* dst = g_t2_12 + (size_t)gw * HID + lane * 8;   // cols [8L, 8L+8)
    *(float4*)(dst)     = make_float4(acc[0] * dd, acc[1] * dd, acc[2] * dd, acc[3] * dd);
    *(float4*)(dst + 4) = make_float4(acc[4] * dd, acc[5] * dd, acc[6] * dd, acc[7] * dd);
}

// ---------------------------------------------------------------------------
// (5,7) Tensor-core GEMM: 3xTF32 mma.sync. BM=128 BN=128 BK=16, 8 warps.
//   LAYER 1: g_h1_16 = fp16(relu(g_t1 @ W1 + b1)), K=128
//   LAYER 2: g_h2    =      relu(g_t2 @ W2 + b2),  K=256
// ---------------------------------------------------------------------------
template <int LAYER>
__global__ void __launch_bounds__(256) k_gemm12(const float* __restrict__ W,
                                                const float* __restrict__ bias) {
    constexpr int K = (LAYER == 1) ? F_IN : HID;
    constexpr int BM = 128, BN = 128, BK = 16;
    constexpr int NT = K / BK;
    constexpr int ASTR = BK + 4;
    constexpr int BSTR = BN + 8;
    const float* A = (LAYER == 1) ? g_t1_12 : g_t2_12;

    __shared__ float As[2][BM][ASTR];
    __shared__ float Bs[2][BK][BSTR];

    const int tid = threadIdx.x;
    const int wid = tid >> 5, lane = tid & 31;
    const int warpM = wid >> 1, warpN = wid & 1;
    const int row0 = blockIdx.y * BM, col0 = blockIdx.x * BN;
    const int gid = lane >> 2, tig = lane & 3;

    float c[2][8][4];
#pragma unroll
    for (int mt = 0; mt < 2; mt++)
#pragma unroll
        for (int nt = 0; nt < 8; nt++)
#pragma unroll
            for (int q = 0; q < 4; q++) c[mt][nt][q] = 0.0f;

    auto load_tile = [&](int buf, int k0) {
#pragma unroll
        for (int i = 0; i < 2; i++) {
            int idx = tid + i * 256;
            int m = idx >> 2, k4 = idx & 3;
            int gm = min(row0 + m, N_NODES - 1);
            cp_async16(&As[buf][m][k4 * 4], A + (size_t)gm * K + k0 + k4 * 4);
        }
#pragma unroll
        for (int i = 0; i < 2; i++) {
            int idx = tid + i * 256;
            int k = idx >> 5, n4 = idx & 31;
            cp_async16(&Bs[buf][k][n4 * 4], W + (size_t)(k0 + k) * HID + col0 + n4 * 4);
        }
        asm volatile("cp.async.commit_group;");
    };

    auto compute = [&](int buf) {
#pragma unroll
        for (int ks = 0; ks < 2; ks++) {
            const int k0 = ks * 8;
            uint32_t ahi[2][4], alo[2][4];
#pragma unroll
            for (int mt = 0; mt < 2; mt++) {
                int m = warpM * 32 + mt * 16;
                float a[4];
                a[0] = As[buf][m + gid][k0 + tig];
                a[1] = As[buf][m + gid + 8][k0 + tig];
                a[2] = As[buf][m + gid][k0 + tig + 4];
                a[3] = As[buf][m + gid + 8][k0 + tig + 4];
#pragma unroll
                for (int q = 0; q < 4; q++) {
                    ahi[mt][q] = f2tf32(a[q]);
                    alo[mt][q] = f2tf32(a[q] - __uint_as_float(ahi[mt][q]));
                }
            }
            uint32_t bhi[8][2], blo[8][2];
#pragma unroll
            for (int nt = 0; nt < 8; nt++) {
                int n = warpN * 64 + nt * 8 + gid;
                float b0 = Bs[buf][k0 + tig][n];
                float b1 = Bs[buf][k0 + tig + 4][n];
                bhi[nt][0] = f2tf32(b0);
                blo[nt][0] = f2tf32(b0 - __uint_as_float(bhi[nt][0]));
                bhi[nt][1] = f2tf32(b1);
                blo[nt][1] = f2tf32(b1 - __uint_as_float(bhi[nt][1]));
            }
#pragma unroll
            for (int mt = 0; mt < 2; mt++)
#pragma unroll
                for (int nt = 0; nt < 8; nt++) {
                    mma_tf32(c[mt][nt], alo[mt], bhi[nt]);
                    mma_tf32(c[mt][nt], ahi[mt], blo[nt]);
                    mma_tf32(c[mt][nt], ahi[mt], bhi[nt]);
                }
        }
    };

    load_tile(0, 0);
    for (int t = 0; t < NT; t++) {
        if (t + 1 < NT) {
            load_tile((t + 1) & 1, (t + 1) * BK);
            asm volatile("cp.async.wait_group 1;");
        } else {
            asm volatile("cp.async.wait_group 0;");
        }
        __syncthreads();
        compute(t & 1);
        __syncthreads();
    }

#pragma unroll
    for (int mt = 0; mt < 2; mt++) {
#pragma unroll
        for (int nt = 0; nt < 8; nt++) {
            int gn = col0 + warpN * 64 + nt * 8 + tig * 2;
            float b0 = __ldg(bias + gn), b1 = __ldg(bias + gn + 1);
            int r0 = row0 + warpM * 32 + mt * 16 + gid;
            int r1 = r0 + 8;
            float v00 = fmaxf(c[mt][nt][0] + b0, 0.f);
            float v01 = fmaxf(c[mt][nt][1] + b1, 0.f);
            float v10 = fmaxf(c[mt][nt][2] + b0, 0.f);
            float v11 = fmaxf(c[mt][nt][3] + b1, 0.f);
            if (LAYER == 1) {
                if (r0 < N_NODES)
                    *(__half2*)(g_h1_16 + (size_t)r0 * HID + gn) = __floats2half2_rn(v00, v01);
                if (r1 < N_NODES)
                    *(__half2*)(g_h1_16 + (size_t)r1 * HID + gn) = __floats2half2_rn(v10, v11);
            } else {
                if (r0 < N_NODES)
                    *(float2*)(g_h2_12 + (size_t)r0 * HID + gn) = make_float2(v00, v01);
                if (r1 < N_NODES)
                    *(float2*)(g_h2_12 + (size_t)r1 * HID + gn) = make_float2(v10, v11);
            }
        }
    }
}

// ---------------------------------------------------------------------------
// (8) Pool: g_sums[batch[node]] += h2[node]
// ---------------------------------------------------------------------------
__global__ void k_pool12(const void* __restrict__ batch) {
    size_t i = (size_t)blockIdx.x * blockDim.x + threadIdx.x;
    if (i >= (size_t)N_NODES * (HID / 4)) return;
    int node = (int)(i >> 6);
    int f4 = (int)(i & 63);
    int g = idx_12(batch, node, g_is6412);
    float4 v = ((const float4*)g_h2_12)[(size_t)node * (HID / 4) + f4];
    red_v4_12(g_sums12 + g * HID + f4 * 4, v);
}

// (9) Final: mean, FC, log_softmax; re-zeros g_sums/g_cnt for next replay
__global__ void k_final12(const float* __restrict__ fcw, const float* __restrict__ fcb,
                          float* __restrict__ out) {
    int g = threadIdx.x;
    if (g >= N_GRAPHS) return;
    float cnt = g_cnt12[g];
    g_cnt12[g] = 0.0f;
    float inv = 1.0f / fmaxf(cnt, 1.0f);
    float l0 = fcb[0], l1 = fcb[1];
#pragma unroll 8
    for (int f = 0; f < HID; f++) {
        float p = g_sums12[g * HID + f] * inv;
        g_sums12[g * HID + f] = 0.0f;
        l0 += p * fcw[f * N_CLS + 0];
        l1 += p * fcw[f * N_CLS + 1];
    }
    float m = fmaxf(l0, l1);
    float lse = m + logf(expf(l0 - m) + expf(l1 - m));
    out[g * N_CLS + 0] = l0 - lse;
    out[g * N_CLS + 1] = l1 - lse;
}

// ---------------------------------------------------------------------------
extern "C" void kernel_launch(void* const* d_in, const int* in_sizes, int n_in,
                              void* d_out, int out_size) {
    const float* x     = (const float*)d_in[0];
    const void*  edges = d_in[1];
    const void*  batch = d_in[2];
    const float* W1    = (const float*)d_in[3];
    const float* b1    = (const float*)d_in[4];
    const float* W2    = (const float*)d_in[5];
    const float* b2    = (const float*)d_in[6];
    const float* fcw   = (const float*)d_in[7];
    const float* fcb   = (const float*)d_in[8];
    float* out = (float*)d_out;

    const int T = 256;
    dim3 gemm_grid(HID / 128, (N_NODES + 127) / 128);
    unsigned warps_grid = (unsigned)(((long long)N_NODES * 32 + 255) / 256);
    unsigned pool_grid  = (unsigned)(((long long)N_NODES * (HID / 4) + T - 1) / T);

    k_deg12<<<(N_EDGES + T - 1) / T, T>>>(edges, batch, x);     // 1 (+ x->fp16)
    k_scan12<<<1, 1024>>>();                                    // 2
    k_fill12<<<(N_EDGES + T - 1) / T, T>>>(edges);              // 3 (+ deg re-zero)
    k_agg1_12<<<warps_grid, 256>>>();                           // 4 <- profiled
    k_gemm12<1><<<gemm_grid, 256>>>(W1, b1);                    // 5
    k_agg2_12<<<warps_grid, 256>>>();                           // 6
    k_gemm12<2><<<gemm_grid, 256>>>(W2, b2);                    // 7
    k_pool12<<<pool_grid, T>>>(batch);                          // 8
    k_final12<<<1, 64>>>(fcw, fcb, out);                        // 9
}

// round 13
// speedup vs baseline: 52.7981x; 1.3038x over previous
#include <cuda_runtime.h>
#include <cuda_fp16.h>
#include <cstdint>
#include <math.h>

#define N_NODES  100000
#define N_EDGES  3200000
#define N_GRAPHS 64
#define F_IN     128
#define HID      256
#define N_CLS    2

// ---------------------------------------------------------------------------
// Scratch — referenced ONLY from device code (GB300 ATS: host-side symbol
// references yield the host shadow; never pass these as kernel args).
// Zero-invariants: g_deg re-zeroed by k_fill; g_sums/g_cnt by k_final.
// ---------------------------------------------------------------------------
__device__ __align__(16) float  g_dinv13[N_NODES];
__device__ __align__(16) int    g_deg13[N_NODES];
__device__ __align__(16) int    g_rowptr13[N_NODES + 1];
__device__ __align__(16) int    g_cursor13[N_NODES];
__device__ __align__(16) int2   g_csr13[N_EDGES];                  // {src, dinv[src]}
__device__ __align__(16) __half g_x16[(size_t)N_NODES * F_IN];     // x fp16
__device__ __align__(16) __half g_t1_16[(size_t)N_NODES * F_IN];   // A~ x, fp16
__device__ __align__(16) __half g_h1_16[(size_t)N_NODES * HID];    // relu(t1 W1+b1), fp16
__device__ __align__(16) __half g_t2_16[(size_t)N_NODES * HID];    // A~ h1, fp16
__device__ __align__(16) float  g_h2_13[(size_t)N_NODES * HID];    // relu(t2 W2+b2), fp32
__device__ __align__(16) __half g_w1t[HID * F_IN];                 // W1^T fp16 [n][k]
__device__ __align__(16) __half g_w2t[HID * HID];                  // W2^T fp16 [n][k]
__device__ __align__(16) float  g_sums13[N_GRAPHS * HID];
__device__ float g_cnt13[N_GRAPHS];
__device__ int   g_is6413;

// ---------------------------------------------------------------------------
__device__ __forceinline__ void red_v4_13(float* p, float4 v) {
    asm volatile("red.global.add.v4.f32 [%0], {%1, %2, %3, %4};"
                 :: "l"(p), "f"(v.x), "f"(v.y), "f"(v.z), "f"(v.w) : "memory");
}
__device__ __forceinline__ int idx_13(const void* p, long long i, int is64) {
    return is64 ? (int)((const long long*)p)[i] : ((const int*)p)[i];
}
__device__ __forceinline__ void mma_f16(float c[4], const uint32_t a[4],
                                        const uint32_t b[2]) {
    asm volatile(
        "mma.sync.aligned.m16n8k16.row.col.f32.f16.f16.f32 "
        "{%0,%1,%2,%3}, {%4,%5,%6,%7}, {%8,%9}, {%0,%1,%2,%3};"
        : "+f"(c[0]), "+f"(c[1]), "+f"(c[2]), "+f"(c[3])
        : "r"(a[0]), "r"(a[1]), "r"(a[2]), "r"(a[3]), "r"(b[0]), "r"(b[1]));
}
__device__ __forceinline__ void cp_async16(void* smem_dst, const void* gsrc) {
    uint32_t d = (uint32_t)__cvta_generic_to_shared(smem_dst);
    asm volatile("cp.async.cg.shared.global [%0], [%1], 16;" :: "r"(d), "l"(gsrc));
}
__device__ __forceinline__ int detect64_13(const void* edges) {
    const long long* p = (const long long*)edges;
    int ok = 1;
#pragma unroll
    for (int j = 0; j < 32; j++) {
        long long v = p[j];
        if (v < 0 || v >= N_NODES) ok = 0;
    }
    return ok;
}

// ---------------------------------------------------------------------------
// (1) degree + per-graph counts + x->fp16 + W1/W2 -> fp16 transposed + detect
// ---------------------------------------------------------------------------
__global__ void k_deg13(const void* __restrict__ edges,
                        const void* __restrict__ batch,
                        const float* __restrict__ X,
                        const float* __restrict__ W1,
                        const float* __restrict__ W2) {
    __shared__ int s_is64;
    if (threadIdx.x == 0) {
        int v = detect64_13(edges);
        s_is64 = v;
        if (blockIdx.x == 0) g_is6413 = v;
    }
    __syncthreads();
    int is64 = s_is64;
    int i = blockIdx.x * blockDim.x + threadIdx.x;
    if (i < N_NODES * (F_IN / 4)) {      // x -> fp16 (vectorized)
        float4 v = ((const float4*)X)[i];
        ((__half2*)g_x16)[i * 2 + 0] = __floats2half2_rn(v.x, v.y);
        ((__half2*)g_x16)[i * 2 + 1] = __floats2half2_rn(v.z, v.w);
    }
    if (i < HID * F_IN) {                // W1^T: w1t[n*128+k] = W1[k*256+n]
        int n = i >> 7, k = i & 127;
        g_w1t[i] = __float2half_rn(W1[(size_t)k * HID + n]);
    }
    if (i < HID * HID) {                 // W2^T: w2t[n*256+k] = W2[k*256+n]
        int n = i >> 8, k = i & 255;
        g_w2t[i] = __float2half_rn(W2[(size_t)k * HID + n]);
    }
    if (i < N_EDGES) {
        int d = idx_13(edges, (long long)N_EDGES + i, is64);
        atomicAdd(&g_deg13[d], 1);
    }
    if (i < N_NODES) {
        int g = idx_13(batch, i, is64);
        atomicAdd(&g_cnt13[g], 1.0f);
    }
}

// (2) single-block scan -> rowptr/cursor; dinv = rsqrt(deg+1)
__global__ void k_scan13() {
    const int T = 1024;
    const int CH = (N_NODES + T - 1) / T;
    __shared__ int part[T];
    int t = threadIdx.x;
    int base = t * CH;
    int local = 0;
    for (int i = 0; i < CH; i++) {
        int idx = base + i;
        if (idx < N_NODES) local += g_deg13[idx];
    }
    part[t] = local;
    __syncthreads();
    for (int off = 1; off < T; off <<= 1) {
        int v = (t >= off) ? part[t - off] : 0;
        __syncthreads();
        if (t >= off) part[t] += v;
        __syncthreads();
    }
    int prefix = (t == 0) ? 0 : part[t - 1];
    for (int i = 0; i < CH; i++) {
        int idx = base + i;
        if (idx < N_NODES) {
            g_rowptr13[idx] = prefix;
            g_cursor13[idx] = prefix;
            prefix += g_deg13[idx];
        }
    }
    if (t == T - 1) g_rowptr13[N_NODES] = part[T - 1];
    __syncthreads();
    for (int i = t; i < N_NODES; i += T)
        g_dinv13[i] = rsqrtf((float)(g_deg13[i] + 1));
}

// (3) CSR fill {src, dinv[src]}; re-zeros g_deg for next replay
__global__ void k_fill13(const void* __restrict__ edges) {
    int e = blockIdx.x * blockDim.x + threadIdx.x;
    if (e < N_NODES) g_deg13[e] = 0;
    if (e >= N_EDGES) return;
    int is64 = g_is6413;
    int s = idx_13(edges, e, is64);
    int d = idx_13(edges, (long long)N_EDGES + e, is64);
    int slot = atomicAdd(&g_cursor13[d], 1);
    g_csr13[slot] = make_int2(s, __float_as_int(g_dinv13[s]));
}

// ---------------------------------------------------------------------------
// (4) agg1: t1 = A~ x   (F=128 fp16 gather, fp32 accum, fp16 out)
// ---------------------------------------------------------------------------
__global__ void __launch_bounds__(256) k_agg1_13() {
    int gw = (blockIdx.x * 256 + threadIdx.x) >> 5;
    int lane = threadIdx.x & 31;
    if (gw >= N_NODES) return;
    int beg = __ldg(&g_rowptr13[gw]);
    int end = __ldg(&g_rowptr13[gw + 1]);
    float dd = __ldg(&g_dinv13[gw]);

    const uint2* Xh = (const uint2*)g_x16;
    float4 acc;
    {
        uint2 u = __ldg(&Xh[(size_t)gw * 32 + lane]);
        float2 f0 = __half22float2(*(const __half2*)&u.x);
        float2 f1 = __half22float2(*(const __half2*)&u.y);
        acc = make_float4(f0.x * dd, f0.y * dd, f1.x * dd, f1.y * dd);
    }
    int j = beg;
    for (; j + 8 <= end; j += 8) {
#pragma unroll
        for (int u8 = 0; u8 < 8; u8++) {
            int2 e = __ldg(&g_csr13[j + u8]);
            float n = __int_as_float(e.y);
            uint2 u = __ldg(&Xh[(size_t)e.x * 32 + lane]);
            float2 f0 = __half22float2(*(const __half2*)&u.x);
            float2 f1 = __half22float2(*(const __half2*)&u.y);
            acc.x += f0.x * n; acc.y += f0.y * n;
            acc.z += f1.x * n; acc.w += f1.y * n;
        }
    }
    for (; j < end; j++) {
        int2 e = __ldg(&g_csr13[j]);
        float n = __int_as_float(e.y);
        uint2 u = __ldg(&Xh[(size_t)e.x * 32 + lane]);
        float2 f0 = __half22float2(*(const __half2*)&u.x);
        float2 f1 = __half22float2(*(const __half2*)&u.y);
        acc.x += f0.x * n; acc.y += f0.y * n;
        acc.z += f1.x * n; acc.w += f1.y * n;
    }
    uint2 o;
    *(__half2*)&o.x = __floats2half2_rn(acc.x * dd, acc.y * dd);
    *(__half2*)&o.y = __floats2half2_rn(acc.z * dd, acc.w * dd);
    ((uint2*)g_t1_16)[(size_t)gw * 32 + lane] = o;
}

// ---------------------------------------------------------------------------
// (6) agg2: t2 = A~ h1   (F=256 fp16 gather, fp32 accum, fp16 out)
// ---------------------------------------------------------------------------
__global__ void __launch_bounds__(256) k_agg2_13() {
    int gw = (blockIdx.x * 256 + threadIdx.x) >> 5;
    int lane = threadIdx.x & 31;
    if (gw >= N_NODES) return;
    int beg = __ldg(&g_rowptr13[gw]);
    int end = __ldg(&g_rowptr13[gw + 1]);
    float dd = __ldg(&g_dinv13[gw]);

    const uint4* Hh = (const uint4*)g_h1_16;
    float acc[8];
    {
        uint4 u = __ldg(&Hh[(size_t)gw * 32 + lane]);
        const __half2* h = (const __half2*)&u;
#pragma unroll
        for (int q = 0; q < 4; q++) {
            float2 f = __half22float2(h[q]);
            acc[q * 2 + 0] = f.x * dd;
            acc[q * 2 + 1] = f.y * dd;
        }
    }
    int j = beg;
    for (; j + 4 <= end; j += 4) {
#pragma unroll
        for (int u4 = 0; u4 < 4; u4++) {
            int2 e = __ldg(&g_csr13[j + u4]);
            float n = __int_as_float(e.y);
            uint4 u = __ldg(&Hh[(size_t)e.x * 32 + lane]);
            const __half2* h = (const __half2*)&u;
#pragma unroll
            for (int q = 0; q < 4; q++) {
                float2 f = __half22float2(h[q]);
                acc[q * 2 + 0] += f.x * n;
                acc[q * 2 + 1] += f.y * n;
            }
        }
    }
    for (; j < end; j++) {
        int2 e = __ldg(&g_csr13[j]);
        float n = __int_as_float(e.y);
        uint4 u = __ldg(&Hh[(size_t)e.x * 32 + lane]);
        const __half2* h = (const __half2*)&u;
#pragma unroll
        for (int q = 0; q < 4; q++) {
            float2 f = __half22float2(h[q]);
            acc[q * 2 + 0] += f.x * n;
            acc[q * 2 + 1] += f.y * n;
        }
    }
    uint4 o;
    __half2* oh = (__half2*)&o;
#pragma unroll
    for (int q = 0; q < 4; q++)
        oh[q] = __floats2half2_rn(acc[q * 2 + 0] * dd, acc[q * 2 + 1] * dd);
    ((uint4*)g_t2_16)[(size_t)gw * 32 + lane] = o;
}

// ---------------------------------------------------------------------------
// (5,7) fp16 tensor-core GEMM: mma.m16n8k16.f32.f16.f16.f32.
// BM=128 BN=128 BK=32, 256 threads = 8 warps (4M x 2N), warp tile 32x64.
// A: t fp16 row-major [node][K]; B: W^T fp16 [n][K] (k-contiguous).
// smem strides padded to 56 halves (112B: 16B-aligned, conflict-free).
//   LAYER 1: h1_16 = fp16(relu(t1 @ W1 + b1)), K=128
//   LAYER 2: h2    =      relu(t2 @ W2 + b2),  K=256 (fp32 out)
// ---------------------------------------------------------------------------
template <int LAYER>
__global__ void __launch_bounds__(256) k_gemm13(const float* __restrict__ bias) {
    constexpr int K = (LAYER == 1) ? F_IN : HID;
    constexpr int BM = 128, BN = 128, BK = 32;
    constexpr int NT = K / BK;
    constexpr int STR = BK + 24;   // 56 halves = 112B
    const __half* A  = (LAYER == 1) ? g_t1_16 : g_t2_16;
    const __half* Bt = (LAYER == 1) ? g_w1t : g_w2t;

    __shared__ __half As[2][BM][STR];
    __shared__ __half Bs[2][BN][STR];

    const int tid = threadIdx.x;
    const int wid = tid >> 5, lane = tid & 31;
    const int warpM = wid >> 1, warpN = wid & 1;
    const int row0 = blockIdx.y * BM, col0 = blockIdx.x * BN;
    const int gid = lane >> 2, tig = lane & 3;

    float c[2][8][4];
#pragma unroll
    for (int mt = 0; mt < 2; mt++)
#pragma unroll
        for (int nt = 0; nt < 8; nt++)
#pragma unroll
            for (int q = 0; q < 4; q++) c[mt][nt][q] = 0.0f;

    auto load_tile = [&](int buf, int k0) {
#pragma unroll
        for (int i = 0; i < 2; i++) {   // A: 128 rows x 4 chunks(8h)
            int idx = tid + i * 256;
            int m = idx >> 2, c8 = idx & 3;
            int gm = min(row0 + m, N_NODES - 1);
            cp_async16(&As[buf][m][c8 * 8], A + (size_t)gm * K + k0 + c8 * 8);
        }
#pragma unroll
        for (int i = 0; i < 2; i++) {   // B: 128 rows(n) x 4 chunks(8h)
            int idx = tid + i * 256;
            int n = idx >> 2, c8 = idx & 3;
            cp_async16(&Bs[buf][n][c8 * 8], Bt + (size_t)(col0 + n) * K + k0 + c8 * 8);
        }
        asm volatile("cp.async.commit_group;");
    };

    auto compute = [&](int buf) {
#pragma unroll
        for (int ks = 0; ks < 2; ks++) {
            const int k0 = ks * 16;
            uint32_t a[2][4];
#pragma unroll
            for (int mt = 0; mt < 2; mt++) {
                int m = warpM * 32 + mt * 16 + gid;
                a[mt][0] = *(const uint32_t*)&As[buf][m][k0 + tig * 2];
                a[mt][1] = *(const uint32_t*)&As[buf][m + 8][k0 + tig * 2];
                a[mt][2] = *(const uint32_t*)&As[buf][m][k0 + tig * 2 + 8];
                a[mt][3] = *(const uint32_t*)&As[buf][m + 8][k0 + tig * 2 + 8];
            }
            uint32_t b[8][2];
#pragma unroll
            for (int nt = 0; nt < 8; nt++) {
                int n = warpN * 64 + nt * 8 + gid;
                b[nt][0] = *(const uint32_t*)&Bs[buf][n][k0 + tig * 2];
                b[nt][1] = *(const uint32_t*)&Bs[buf][n][k0 + tig * 2 + 8];
            }
#pragma unroll
            for (int mt = 0; mt < 2; mt++)
#pragma unroll
                for (int nt = 0; nt < 8; nt++)
                    mma_f16(c[mt][nt], a[mt], b[nt]);
        }
    };

    load_tile(0, 0);
    for (int t = 0; t < NT; t++) {
        if (t + 1 < NT) {
            load_tile((t + 1) & 1, (t + 1) * BK);
            asm volatile("cp.async.wait_group 1;");
        } else {
            asm volatile("cp.async.wait_group 0;");
        }
        __syncthreads();
        compute(t & 1);
        __syncthreads();
    }

#pragma unroll
    for (int mt = 0; mt < 2; mt++) {
#pragma unroll
        for (int nt = 0; nt < 8; nt++) {
            int gn = col0 + warpN * 64 + nt * 8 + tig * 2;
            float b0 = __ldg(bias + gn), b1 = __ldg(bias + gn + 1);
            int r0 = row0 + warpM * 32 + mt * 16 + gid;
            int r1 = r0 + 8;
            float v00 = fmaxf(c[mt][nt][0] + b0, 0.f);
            float v01 = fmaxf(c[mt][nt][1] + b1, 0.f);
            float v10 = fmaxf(c[mt][nt][2] + b0, 0.f);
            float v11 = fmaxf(c[mt][nt][3] + b1, 0.f);
            if (LAYER == 1) {
                if (r0 < N_NODES)
                    *(__half2*)(g_h1_16 + (size_t)r0 * HID + gn) = __floats2half2_rn(v00, v01);
                if (r1 < N_NODES)
                    *(__half2*)(g_h1_16 + (size_t)r1 * HID + gn) = __floats2half2_rn(v10, v11);
            } else {
                if (r0 < N_NODES)
                    *(float2*)(g_h2_13 + (size_t)r0 * HID + gn) = make_float2(v00, v01);
                if (r1 < N_NODES)
                    *(float2*)(g_h2_13 + (size_t)r1 * HID + gn) = make_float2(v10, v11);
            }
        }
    }
}

// ---------------------------------------------------------------------------
// (8) Pool: g_sums[batch[node]] += h2[node]
// ---------------------------------------------------------------------------
__global__ void k_pool13(const void* __restrict__ batch) {
    size_t i = (size_t)blockIdx.x * blockDim.x + threadIdx.x;
    if (i >= (size_t)N_NODES * (HID / 4)) return;
    int node = (int)(i >> 6);
    int f4 = (int)(i & 63);
    int g = idx_13(batch, node, g_is6413);
    float4 v = ((const float4*)g_h2_13)[(size_t)node * (HID / 4) + f4];
    red_v4_13(g_sums13 + g * HID + f4 * 4, v);
}

// (9) Final: mean, FC, log_softmax; re-zeros g_sums/g_cnt for next replay
__global__ void k_final13(const float* __restrict__ fcw, const float* __restrict__ fcb,
                          float* __restrict__ out) {
    int g = threadIdx.x;
    if (g >= N_GRAPHS) return;
    float cnt = g_cnt13[g];
    g_cnt13[g] = 0.0f;
    float inv = 1.0f / fmaxf(cnt, 1.0f);
    float l0 = fcb[0], l1 = fcb[1];
#pragma unroll 8
    for (int f = 0; f < HID; f++) {
        float p = g_sums13[g * HID + f] * inv;
        g_sums13[g * HID + f] = 0.0f;
        l0 += p * fcw[f * N_CLS + 0];
        l1 += p * fcw[f * N_CLS + 1];
    }
    float m = fmaxf(l0, l1);
    float lse = m + logf(expf(l0 - m) + expf(l1 - m));
    out[g * N_CLS + 0] = l0 - lse;
    out[g * N_CLS + 1] = l1 - lse;
}

// ---------------------------------------------------------------------------
extern "C" void kernel_launch(void* const* d_in, const int* in_sizes, int n_in,
                              void* d_out, int out_size) {
    const float* x     = (const float*)d_in[0];
    const void*  edges = d_in[1];
    const void*  batch = d_in[2];
    const float* W1    = (const float*)d_in[3];
    const float* b1    = (const float*)d_in[4];
    const float* W2    = (const float*)d_in[5];
    const float* b2    = (const float*)d_in[6];
    const float* fcw   = (const float*)d_in[7];
    const float* fcb   = (const float*)d_in[8];
    float* out = (float*)d_out;

    const int T = 256;
    dim3 gemm_grid(HID / 128, (N_NODES + 127) / 128);
    unsigned warps_grid = (unsigned)(((long long)N_NODES * 32 + 255) / 256);
    unsigned pool_grid  = (unsigned)(((long long)N_NODES * (HID / 4) + T - 1) / T);

    k_deg13<<<(N_EDGES + T - 1) / T, T>>>(edges, batch, x, W1, W2);  // 1
    k_scan13<<<1, 1024>>>();                                         // 2
    k_fill13<<<(N_EDGES + T - 1) / T, T>>>(edges);                   // 3
    k_agg1_13<<<warps_grid, 256>>>();                                // 4 <- profiled
    k_gemm13<1><<<gemm_grid, 256>>>(b1);                             // 5
    k_agg2_13<<<warps_grid, 256>>>();                                // 6
    k_gemm13<2><<<gemm_grid, 256>>>(b2);                             // 7
    k_pool13<<<pool_grid, T>>>(batch);                               // 8
    k_final13<<<1, 64>>>(fcw, fcb, out);                             // 9
}

// round 14
// speedup vs baseline: 60.2298x; 1.1408x over previous
#include <cuda_runtime.h>
#include <cuda_fp16.h>
#include <cstdint>
#include <math.h>

#define N_NODES  100000
#define N_EDGES  3200000
#define N_GRAPHS 64
#define F_IN     128
#define HID      256
#define N_CLS    2

// ---------------------------------------------------------------------------
// Scratch — referenced ONLY from device code (GB300 ATS: host-side symbol
// references yield the host shadow; never pass these as kernel args).
// Zero-invariants: g_deg re-zeroed by k_fill; g_sums/g_cnt by k_final.
// ---------------------------------------------------------------------------
__device__ __align__(16) float  g_dinv14[N_NODES];
__device__ __align__(16) int    g_deg14[N_NODES];
__device__ __align__(16) int    g_rowptr14[N_NODES + 1];
__device__ __align__(16) int    g_cursor14[N_NODES];
__device__ __align__(16) int2   g_csr14[N_EDGES];                  // {src, dinv[src]}
__device__ __align__(16) __half g_x16[(size_t)N_NODES * F_IN];     // x fp16
__device__ __align__(16) __half g_t1_16[(size_t)N_NODES * F_IN];   // A~ x, fp16
__device__ __align__(16) __half g_h1_16[(size_t)N_NODES * HID];    // relu(t1 W1+b1), fp16
__device__ __align__(16) __half g_t2_16[(size_t)N_NODES * HID];    // A~ h1, fp16
__device__ __align__(16) __half g_w1t[HID * F_IN];                 // W1^T fp16 [n][k]
__device__ __align__(16) __half g_w2t[HID * HID];                  // W2^T fp16 [n][k]
__device__ __align__(16) float  g_sums14[N_GRAPHS * HID];
__device__ float g_cnt14[N_GRAPHS];
__device__ int   g_is6414;

// ---------------------------------------------------------------------------
__device__ __forceinline__ void red_v2_14(float* p, float a, float b) {
    asm volatile("red.global.add.v2.f32 [%0], {%1, %2};"
                 :: "l"(p), "f"(a), "f"(b) : "memory");
}
__device__ __forceinline__ int idx_14(const void* p, long long i, int is64) {
    return is64 ? (int)((const long long*)p)[i] : ((const int*)p)[i];
}
__device__ __forceinline__ void mma_f16(float c[4], const uint32_t a[4],
                                        const uint32_t b[2]) {
    asm volatile(
        "mma.sync.aligned.m16n8k16.row.col.f32.f16.f16.f32 "
        "{%0,%1,%2,%3}, {%4,%5,%6,%7}, {%8,%9}, {%0,%1,%2,%3};"
        : "+f"(c[0]), "+f"(c[1]), "+f"(c[2]), "+f"(c[3])
        : "r"(a[0]), "r"(a[1]), "r"(a[2]), "r"(a[3]), "r"(b[0]), "r"(b[1]));
}
__device__ __forceinline__ void cp_async16(void* smem_dst, const void* gsrc) {
    uint32_t d = (uint32_t)__cvta_generic_to_shared(smem_dst);
    asm volatile("cp.async.cg.shared.global [%0], [%1], 16;" :: "r"(d), "l"(gsrc));
}
__device__ __forceinline__ int detect64_14(const void* edges) {
    const long long* p = (const long long*)edges;
    int ok = 1;
#pragma unroll
    for (int j = 0; j < 32; j++) {
        long long v = p[j];
        if (v < 0 || v >= N_NODES) ok = 0;
    }
    return ok;
}

// ---------------------------------------------------------------------------
// (1) degree + per-graph counts + x->fp16 + W1/W2 -> fp16 transposed + detect
// ---------------------------------------------------------------------------
__global__ void k_deg14(const void* __restrict__ edges,
                        const void* __restrict__ batch,
                        const float* __restrict__ X,
                        const float* __restrict__ W1,
                        const float* __restrict__ W2) {
    __shared__ int s_is64;
    if (threadIdx.x == 0) {
        int v = detect64_14(edges);
        s_is64 = v;
        if (blockIdx.x == 0) g_is6414 = v;
    }
    __syncthreads();
    int is64 = s_is64;
    int i = blockIdx.x * blockDim.x + threadIdx.x;
    if (i < N_NODES * (F_IN / 4)) {      // x -> fp16 (vectorized)
        float4 v = ((const float4*)X)[i];
        ((__half2*)g_x16)[i * 2 + 0] = __floats2half2_rn(v.x, v.y);
        ((__half2*)g_x16)[i * 2 + 1] = __floats2half2_rn(v.z, v.w);
    }
    if (i < HID * F_IN) {                // W1^T: w1t[n*128+k] = W1[k*256+n]
        int n = i >> 7, k = i & 127;
        g_w1t[i] = __float2half_rn(W1[(size_t)k * HID + n]);
    }
    if (i < HID * HID) {                 // W2^T: w2t[n*256+k] = W2[k*256+n]
        int n = i >> 8, k = i & 255;
        g_w2t[i] = __float2half_rn(W2[(size_t)k * HID + n]);
    }
    if (i < N_EDGES) {
        int d = idx_14(edges, (long long)N_EDGES + i, is64);
        atomicAdd(&g_deg14[d], 1);
    }
    if (i < N_NODES) {
        int g = idx_14(batch, i, is64);
        atomicAdd(&g_cnt14[g], 1.0f);
    }
}

// (2) single-block scan -> rowptr/cursor; dinv = rsqrt(deg+1)
__global__ void k_scan14() {
    const int T = 1024;
    const int CH = (N_NODES + T - 1) / T;
    __shared__ int part[T];
    int t = threadIdx.x;
    int base = t * CH;
    int local = 0;
    for (int i = 0; i < CH; i++) {
        int idx = base + i;
        if (idx < N_NODES) local += g_deg14[idx];
    }
    part[t] = local;
    __syncthreads();
    for (int off = 1; off < T; off <<= 1) {
        int v = (t >= off) ? part[t - off] : 0;
        __syncthreads();
        if (t >= off) part[t] += v;
        __syncthreads();
    }
    int prefix = (t == 0) ? 0 : part[t - 1];
    for (int i = 0; i < CH; i++) {
        int idx = base + i;
        if (idx < N_NODES) {
            g_rowptr14[idx] = prefix;
            g_cursor14[idx] = prefix;
            prefix += g_deg14[idx];
        }
    }
    if (t == T - 1) g_rowptr14[N_NODES] = part[T - 1];
    __syncthreads();
    for (int i = t; i < N_NODES; i += T)
        g_dinv14[i] = rsqrtf((float)(g_deg14[i] + 1));
}

// (3) CSR fill {src, dinv[src]}; re-zeros g_deg for next replay
__global__ void k_fill14(const void* __restrict__ edges) {
    int e = blockIdx.x * blockDim.x + threadIdx.x;
    if (e < N_NODES) g_deg14[e] = 0;
    if (e >= N_EDGES) return;
    int is64 = g_is6414;
    int s = idx_14(edges, e, is64);
    int d = idx_14(edges, (long long)N_EDGES + e, is64);
    int slot = atomicAdd(&g_cursor14[d], 1);
    g_csr14[slot] = make_int2(s, __float_as_int(g_dinv14[s]));
}

// ---------------------------------------------------------------------------
// (4) agg1: t1 = A~ x   (F=128 fp16 gather, fp32 accum, fp16 out)
// ---------------------------------------------------------------------------
__global__ void __launch_bounds__(256) k_agg1_14() {
    int gw = (blockIdx.x * 256 + threadIdx.x) >> 5;
    int lane = threadIdx.x & 31;
    if (gw >= N_NODES) return;
    int beg = __ldg(&g_rowptr14[gw]);
    int end = __ldg(&g_rowptr14[gw + 1]);
    float dd = __ldg(&g_dinv14[gw]);

    const uint2* Xh = (const uint2*)g_x16;
    float4 acc;
    {
        uint2 u = __ldg(&Xh[(size_t)gw * 32 + lane]);
        float2 f0 = __half22float2(*(const __half2*)&u.x);
        float2 f1 = __half22float2(*(const __half2*)&u.y);
        acc = make_float4(f0.x * dd, f0.y * dd, f1.x * dd, f1.y * dd);
    }
    int j = beg;
    for (; j + 8 <= end; j += 8) {
#pragma unroll
        for (int u8 = 0; u8 < 8; u8++) {
            int2 e = __ldg(&g_csr14[j + u8]);
            float n = __int_as_float(e.y);
            uint2 u = __ldg(&Xh[(size_t)e.x * 32 + lane]);
            float2 f0 = __half22float2(*(const __half2*)&u.x);
            float2 f1 = __half22float2(*(const __half2*)&u.y);
            acc.x += f0.x * n; acc.y += f0.y * n;
            acc.z += f1.x * n; acc.w += f1.y * n;
        }
    }
    for (; j < end; j++) {
        int2 e = __ldg(&g_csr14[j]);
        float n = __int_as_float(e.y);
        uint2 u = __ldg(&Xh[(size_t)e.x * 32 + lane]);
        float2 f0 = __half22float2(*(const __half2*)&u.x);
        float2 f1 = __half22float2(*(const __half2*)&u.y);
        acc.x += f0.x * n; acc.y += f0.y * n;
        acc.z += f1.x * n; acc.w += f1.y * n;
    }
    uint2 o;
    *(__half2*)&o.x = __floats2half2_rn(acc.x * dd, acc.y * dd);
    *(__half2*)&o.y = __floats2half2_rn(acc.z * dd, acc.w * dd);
    ((uint2*)g_t1_16)[(size_t)gw * 32 + lane] = o;
}

// ---------------------------------------------------------------------------
// (6) agg2: t2 = A~ h1   (F=256 fp16 gather, fp32 accum, fp16 out)
// ---------------------------------------------------------------------------
__global__ void __launch_bounds__(256) k_agg2_14() {
    int gw = (blockIdx.x * 256 + threadIdx.x) >> 5;
    int lane = threadIdx.x & 31;
    if (gw >= N_NODES) return;
    int beg = __ldg(&g_rowptr14[gw]);
    int end = __ldg(&g_rowptr14[gw + 1]);
    float dd = __ldg(&g_dinv14[gw]);

    const uint4* Hh = (const uint4*)g_h1_16;
    float acc[8];
    {
        uint4 u = __ldg(&Hh[(size_t)gw * 32 + lane]);
        const __half2* h = (const __half2*)&u;
#pragma unroll
        for (int q = 0; q < 4; q++) {
            float2 f = __half22float2(h[q]);
            acc[q * 2 + 0] = f.x * dd;
            acc[q * 2 + 1] = f.y * dd;
        }
    }
    int j = beg;
    for (; j + 4 <= end; j += 4) {
#pragma unroll
        for (int u4 = 0; u4 < 4; u4++) {
            int2 e = __ldg(&g_csr14[j + u4]);
            float n = __int_as_float(e.y);
            uint4 u = __ldg(&Hh[(size_t)e.x * 32 + lane]);
            const __half2* h = (const __half2*)&u;
#pragma unroll
            for (int q = 0; q < 4; q++) {
                float2 f = __half22float2(h[q]);
                acc[q * 2 + 0] += f.x * n;
                acc[q * 2 + 1] += f.y * n;
            }
        }
    }
    for (; j < end; j++) {
        int2 e = __ldg(&g_csr14[j]);
        float n = __int_as_float(e.y);
        uint4 u = __ldg(&Hh[(size_t)e.x * 32 + lane]);
        const __half2* h = (const __half2*)&u;
#pragma unroll
        for (int q = 0; q < 4; q++) {
            float2 f = __half22float2(h[q]);
            acc[q * 2 + 0] += f.x * n;
            acc[q * 2 + 1] += f.y * n;
        }
    }
    uint4 o;
    __half2* oh = (__half2*)&o;
#pragma unroll
    for (int q = 0; q < 4; q++)
        oh[q] = __floats2half2_rn(acc[q * 2 + 0] * dd, acc[q * 2 + 1] * dd);
    ((uint4*)g_t2_16)[(size_t)gw * 32 + lane] = o;
}

// ---------------------------------------------------------------------------
// (5,7) fp16 tensor-core GEMM: mma.m16n8k16.f32.f16.f16.f32.
// BM=128 BN=128 BK=32, 256 threads = 8 warps (4M x 2N), warp tile 32x64.
//   LAYER 1: h1_16 = fp16(relu(t1 @ W1 + b1)), K=128
//   LAYER 2: relu(t2 @ W2 + b2) FUSED-POOLED into g_sums (no h2), K=256
// ---------------------------------------------------------------------------
template <int LAYER>
__global__ void __launch_bounds__(256) k_gemm14(const float* __restrict__ bias,
                                                const void* __restrict__ batch) {
    constexpr int K = (LAYER == 1) ? F_IN : HID;
    constexpr int BM = 128, BN = 128, BK = 32;
    constexpr int NT = K / BK;
    constexpr int STR = BK + 24;   // 56 halves = 112B
    const __half* A  = (LAYER == 1) ? g_t1_16 : g_t2_16;
    const __half* Bt = (LAYER == 1) ? g_w1t : g_w2t;

    __shared__ __half As[2][BM][STR];
    __shared__ __half Bs[2][BN][STR];

    const int tid = threadIdx.x;
    const int wid = tid >> 5, lane = tid & 31;
    const int warpM = wid >> 1, warpN = wid & 1;
    const int row0 = blockIdx.y * BM, col0 = blockIdx.x * BN;
    const int gid = lane >> 2, tig = lane & 3;

    float c[2][8][4];
#pragma unroll
    for (int mt = 0; mt < 2; mt++)
#pragma unroll
        for (int nt = 0; nt < 8; nt++)
#pragma unroll
            for (int q = 0; q < 4; q++) c[mt][nt][q] = 0.0f;

    auto load_tile = [&](int buf, int k0) {
#pragma unroll
        for (int i = 0; i < 2; i++) {   // A: 128 rows x 4 chunks(8h)
            int idx = tid + i * 256;
            int m = idx >> 2, c8 = idx & 3;
            int gm = min(row0 + m, N_NODES - 1);
            cp_async16(&As[buf][m][c8 * 8], A + (size_t)gm * K + k0 + c8 * 8);
        }
#pragma unroll
        for (int i = 0; i < 2; i++) {   // B: 128 rows(n) x 4 chunks(8h)
            int idx = tid + i * 256;
            int n = idx >> 2, c8 = idx & 3;
            cp_async16(&Bs[buf][n][c8 * 8], Bt + (size_t)(col0 + n) * K + k0 + c8 * 8);
        }
        asm volatile("cp.async.commit_group;");
    };

    auto compute = [&](int buf) {
#pragma unroll
        for (int ks = 0; ks < 2; ks++) {
            const int k0 = ks * 16;
            uint32_t a[2][4];
#pragma unroll
            for (int mt = 0; mt < 2; mt++) {
                int m = warpM * 32 + mt * 16 + gid;
                a[mt][0] = *(const uint32_t*)&As[buf][m][k0 + tig * 2];
                a[mt][1] = *(const uint32_t*)&As[buf][m + 8][k0 + tig * 2];
                a[mt][2] = *(const uint32_t*)&As[buf][m][k0 + tig * 2 + 8];
                a[mt][3] = *(const uint32_t*)&As[buf][m + 8][k0 + tig * 2 + 8];
            }
            uint32_t b[8][2];
#pragma unroll
            for (int nt = 0; nt < 8; nt++) {
                int n = warpN * 64 + nt * 8 + gid;
                b[nt][0] = *(const uint32_t*)&Bs[buf][n][k0 + tig * 2];
                b[nt][1] = *(const uint32_t*)&Bs[buf][n][k0 + tig * 2 + 8];
            }
#pragma unroll
            for (int mt = 0; mt < 2; mt++)
#pragma unroll
                for (int nt = 0; nt < 8; nt++)
                    mma_f16(c[mt][nt], a[mt], b[nt]);
        }
    };

    load_tile(0, 0);
    for (int t = 0; t < NT; t++) {
        if (t + 1 < NT) {
            load_tile((t + 1) & 1, (t + 1) * BK);
            asm volatile("cp.async.wait_group 1;");
        } else {
            asm volatile("cp.async.wait_group 0;");
        }
        __syncthreads();
        compute(t & 1);
        __syncthreads();
    }

    if (LAYER == 1) {
#pragma unroll
        for (int mt = 0; mt < 2; mt++) {
#pragma unroll
            for (int nt = 0; nt < 8; nt++) {
                int gn = col0 + warpN * 64 + nt * 8 + tig * 2;
                float b0 = __ldg(bias + gn), b1 = __ldg(bias + gn + 1);
                int r0 = row0 + warpM * 32 + mt * 16 + gid;
                int r1 = r0 + 8;
                if (r0 < N_NODES)
                    *(__half2*)(g_h1_16 + (size_t)r0 * HID + gn) =
                        __floats2half2_rn(fmaxf(c[mt][nt][0] + b0, 0.f),
                                          fmaxf(c[mt][nt][1] + b1, 0.f));
                if (r1 < N_NODES)
                    *(__half2*)(g_h1_16 + (size_t)r1 * HID + gn) =
                        __floats2half2_rn(fmaxf(c[mt][nt][2] + b0, 0.f),
                                          fmaxf(c[mt][nt][3] + b1, 0.f));
            }
        }
    } else {
        // fused mean-pool numerator: relu rows red.v2'ed into g_sums[graph]
        int is64 = g_is6414;
#pragma unroll
        for (int mt = 0; mt < 2; mt++) {
            int r0 = row0 + warpM * 32 + mt * 16 + gid;
            int r1 = r0 + 8;
            bool ok0 = r0 < N_NODES, ok1 = r1 < N_NODES;
            int g0 = ok0 ? idx_14(batch, r0, is64) : 0;
            int g1 = ok1 ? idx_14(batch, r1, is64) : 0;
#pragma unroll
            for (int nt = 0; nt < 8; nt++) {
                int gn = col0 + warpN * 64 + nt * 8 + tig * 2;
                float b0 = __ldg(bias + gn), b1 = __ldg(bias + gn + 1);
                float v00 = fmaxf(c[mt][nt][0] + b0, 0.f);
                float v01 = fmaxf(c[mt][nt][1] + b1, 0.f);
                float v10 = fmaxf(c[mt][nt][2] + b0, 0.f);
                float v11 = fmaxf(c[mt][nt][3] + b1, 0.f);
                if (ok0 && ok1 && g0 == g1) {
                    red_v2_14(g_sums14 + g0 * HID + gn, v00 + v10, v01 + v11);
                } else {
                    if (ok0) red_v2_14(g_sums14 + g0 * HID + gn, v00, v01);
                    if (ok1) red_v2_14(g_sums14 + g1 * HID + gn, v10, v11);
                }
            }
        }
    }
}

// ---------------------------------------------------------------------------
// (8) Final: mean, FC, log_softmax; re-zeros g_sums/g_cnt for next replay
// ---------------------------------------------------------------------------
__global__ void k_final14(const float* __restrict__ fcw, const float* __restrict__ fcb,
                          float* __restrict__ out) {
    int g = threadIdx.x;
    if (g >= N_GRAPHS) return;
    float cnt = g_cnt14[g];
    g_cnt14[g] = 0.0f;
    float inv = 1.0f / fmaxf(cnt, 1.0f);
    float l0 = fcb[0], l1 = fcb[1];
#pragma unroll 8
    for (int f = 0; f < HID; f++) {
        float p = g_sums14[g * HID + f] * inv;
        g_sums14[g * HID + f] = 0.0f;
        l0 += p * fcw[f * N_CLS + 0];
        l1 += p * fcw[f * N_CLS + 1];
    }
    float m = fmaxf(l0, l1);
    float lse = m + logf(expf(l0 - m) + expf(l1 - m));
    out[g * N_CLS + 0] = l0 - lse;
    out[g * N_CLS + 1] = l1 - lse;
}

// ---------------------------------------------------------------------------
extern "C" void kernel_launch(void* const* d_in, const int* in_sizes, int n_in,
                              void* d_out, int out_size) {
    const float* x     = (const float*)d_in[0];
    const void*  edges = d_in[1];
    const void*  batch = d_in[2];
    const float* W1    = (const float*)d_in[3];
    const float* b1    = (const float*)d_in[4];
    const float* W2    = (const float*)d_in[5];
    const float* b2    = (const float*)d_in[6];
    const float* fcw   = (const float*)d_in[7];
    const float* fcb   = (const float*)d_in[8];
    float* out = (float*)d_out;

    const int T = 256;
    dim3 gemm_grid(HID / 128, (N_NODES + 127) / 128);
    unsigned warps_grid = (unsigned)(((long long)N_NODES * 32 + 255) / 256);

    k_deg14<<<(N_EDGES + T - 1) / T, T>>>(edges, batch, x, W1, W2);  // 1
    k_scan14<<<1, 1024>>>();                                         // 2
    k_fill14<<<(N_EDGES + T - 1) / T, T>>>(edges);                   // 3
    k_agg1_14<<<warps_grid, 256>>>();                                // 4 <- profiled
    k_gemm14<1><<<gemm_grid, 256>>>(b1, batch);                      // 5
    k_agg2_14<<<warps_grid, 256>>>();                                // 6
    k_gemm14<2><<<gemm_grid, 256>>>(b2, batch);                      // 7 (+fused pool)
    k_final14<<<1, 64>>>(fcw, fcb, out);                             // 8
}

// round 15
// speedup vs baseline: 60.8337x; 1.0100x over previous
#include <cuda_runtime.h>
#include <cuda_fp16.h>
#include <cstdint>
#include <math.h>

#define N_NODES  100000
#define N_EDGES  3200000
#define N_GRAPHS 64
#define F_IN     128
#define HID      256
#define N_CLS    2

// ---------------------------------------------------------------------------
// Scratch — referenced ONLY from device code (GB300 ATS: host-side symbol
// references yield the host shadow; never pass these as kernel args).
// Zero-invariants: g_deg re-zeroed by k_fill; g_sums/g_cnt by k_final.
// ---------------------------------------------------------------------------
__device__ __align__(16) float  g_dinv15[N_NODES];
__device__ __align__(16) int    g_deg15[N_NODES];
__device__ __align__(16) int    g_rowptr15[N_NODES + 1];
__device__ __align__(16) int    g_cursor15[N_NODES];
__device__ __align__(16) int2   g_csr15[N_EDGES];                  // {src, dinv[src]}
__device__ __align__(16) __half g_x16[(size_t)N_NODES * F_IN];     // x fp16
__device__ __align__(16) __half g_t1_16[(size_t)N_NODES * F_IN];   // A~ x, fp16
__device__ __align__(16) __half g_h1_16[(size_t)N_NODES * HID];    // relu(t1 W1+b1), fp16
__device__ __align__(16) __half g_t2_16[(size_t)N_NODES * HID];    // A~ h1, fp16
__device__ __align__(16) __half g_w1t[HID * F_IN];                 // W1^T fp16 [n][k]
__device__ __align__(16) __half g_w2t[HID * HID];                  // W2^T fp16 [n][k]
__device__ __align__(16) float  g_sums15[N_GRAPHS * HID];
__device__ float g_cnt15[N_GRAPHS];
__device__ int   g_is6415;

// ---------------------------------------------------------------------------
__device__ __forceinline__ void red_v2_15(float* p, float a, float b) {
    asm volatile("red.global.add.v2.f32 [%0], {%1, %2};"
                 :: "l"(p), "f"(a), "f"(b) : "memory");
}
__device__ __forceinline__ int idx_15(const void* p, long long i, int is64) {
    return is64 ? (int)((const long long*)p)[i] : ((const int*)p)[i];
}
__device__ __forceinline__ void mma_f16(float c[4], const uint32_t a[4],
                                        const uint32_t b[2]) {
    asm volatile(
        "mma.sync.aligned.m16n8k16.row.col.f32.f16.f16.f32 "
        "{%0,%1,%2,%3}, {%4,%5,%6,%7}, {%8,%9}, {%0,%1,%2,%3};"
        : "+f"(c[0]), "+f"(c[1]), "+f"(c[2]), "+f"(c[3])
        : "r"(a[0]), "r"(a[1]), "r"(a[2]), "r"(a[3]), "r"(b[0]), "r"(b[1]));
}
__device__ __forceinline__ void ldsm_x4(uint32_t& r0, uint32_t& r1,
                                        uint32_t& r2, uint32_t& r3, uint32_t addr) {
    asm volatile("ldmatrix.sync.aligned.m8n8.x4.shared.b16 {%0,%1,%2,%3}, [%4];"
                 : "=r"(r0), "=r"(r1), "=r"(r2), "=r"(r3) : "r"(addr));
}
__device__ __forceinline__ uint32_t smem_u32(const void* p) {
    return (uint32_t)__cvta_generic_to_shared(p);
}
__device__ __forceinline__ void cp_async16(void* smem_dst, const void* gsrc) {
    uint32_t d = (uint32_t)__cvta_generic_to_shared(smem_dst);
    asm volatile("cp.async.cg.shared.global [%0], [%1], 16;" :: "r"(d), "l"(gsrc));
}
__device__ __forceinline__ int detect64_15(const void* edges) {
    const long long* p = (const long long*)edges;
    int ok = 1;
#pragma unroll
    for (int j = 0; j < 32; j++) {
        long long v = p[j];
        if (v < 0 || v >= N_NODES) ok = 0;
    }
    return ok;
}

// ---------------------------------------------------------------------------
// (1) degree + per-graph counts + x->fp16 + W1/W2 -> fp16 transposed + detect
// ---------------------------------------------------------------------------
__global__ void k_deg15(const void* __restrict__ edges,
                        const void* __restrict__ batch,
                        const float* __restrict__ X,
                        const float* __restrict__ W1,
                        const float* __restrict__ W2) {
    __shared__ int s_is64;
    if (threadIdx.x == 0) {
        int v = detect64_15(edges);
        s_is64 = v;
        if (blockIdx.x == 0) g_is6415 = v;
    }
    __syncthreads();
    int is64 = s_is64;
    int i = blockIdx.x * blockDim.x + threadIdx.x;
    if (i < N_NODES * (F_IN / 4)) {      // x -> fp16 (vectorized)
        float4 v = ((const float4*)X)[i];
        ((__half2*)g_x16)[i * 2 + 0] = __floats2half2_rn(v.x, v.y);
        ((__half2*)g_x16)[i * 2 + 1] = __floats2half2_rn(v.z, v.w);
    }
    if (i < HID * F_IN) {                // W1^T: w1t[n*128+k] = W1[k*256+n]
        int n = i >> 7, k = i & 127;
        g_w1t[i] = __float2half_rn(W1[(size_t)k * HID + n]);
    }
    if (i < HID * HID) {                 // W2^T: w2t[n*256+k] = W2[k*256+n]
        int n = i >> 8, k = i & 255;
        g_w2t[i] = __float2half_rn(W2[(size_t)k * HID + n]);
    }
    if (i < N_EDGES) {
        int d = idx_15(edges, (long long)N_EDGES + i, is64);
        atomicAdd(&g_deg15[d], 1);
    }
    if (i < N_NODES) {
        int g = idx_15(batch, i, is64);
        atomicAdd(&g_cnt15[g], 1.0f);
    }
}

// (2) single-block scan -> rowptr/cursor; dinv = rsqrt(deg+1)
__global__ void k_scan15() {
    const int T = 1024;
    const int CH = (N_NODES + T - 1) / T;
    __shared__ int part[T];
    int t = threadIdx.x;
    int base = t * CH;
    int local = 0;
    for (int i = 0; i < CH; i++) {
        int idx = base + i;
        if (idx < N_NODES) local += g_deg15[idx];
    }
    part[t] = local;
    __syncthreads();
    for (int off = 1; off < T; off <<= 1) {
        int v = (t >= off) ? part[t - off] : 0;
        __syncthreads();
        if (t >= off) part[t] += v;
        __syncthreads();
    }
    int prefix = (t == 0) ? 0 : part[t - 1];
    for (int i = 0; i < CH; i++) {
        int idx = base + i;
        if (idx < N_NODES) {
            g_rowptr15[idx] = prefix;
            g_cursor15[idx] = prefix;
            prefix += g_deg15[idx];
        }
    }
    if (t == T - 1) g_rowptr15[N_NODES] = part[T - 1];
    __syncthreads();
    for (int i = t; i < N_NODES; i += T)
        g_dinv15[i] = rsqrtf((float)(g_deg15[i] + 1));
}

// (3) CSR fill {src, dinv[src]}; re-zeros g_deg for next replay
__global__ void k_fill15(const void* __restrict__ edges) {
    int e = blockIdx.x * blockDim.x + threadIdx.x;
    if (e < N_NODES) g_deg15[e] = 0;
    if (e >= N_EDGES) return;
    int is64 = g_is6415;
    int s = idx_15(edges, e, is64);
    int d = idx_15(edges, (long long)N_EDGES + e, is64);
    int slot = atomicAdd(&g_cursor15[d], 1);
    g_csr15[slot] = make_int2(s, __float_as_int(g_dinv15[s]));
}

// ---------------------------------------------------------------------------
// (4) agg1: t1 = A~ x   (F=128 fp16 gather, fp32 accum, fp16 out)
// ---------------------------------------------------------------------------
__global__ void __launch_bounds__(256) k_agg1_15() {
    int gw = (blockIdx.x * 256 + threadIdx.x) >> 5;
    int lane = threadIdx.x & 31;
    if (gw >= N_NODES) return;
    int beg = __ldg(&g_rowptr15[gw]);
    int end = __ldg(&g_rowptr15[gw + 1]);
    float dd = __ldg(&g_dinv15[gw]);

    const uint2* Xh = (const uint2*)g_x16;
    float4 acc;
    {
        uint2 u = __ldg(&Xh[(size_t)gw * 32 + lane]);
        float2 f0 = __half22float2(*(const __half2*)&u.x);
        float2 f1 = __half22float2(*(const __half2*)&u.y);
        acc = make_float4(f0.x * dd, f0.y * dd, f1.x * dd, f1.y * dd);
    }
    int j = beg;
    for (; j + 8 <= end; j += 8) {
#pragma unroll
        for (int u8 = 0; u8 < 8; u8++) {
            int2 e = __ldg(&g_csr15[j + u8]);
            float n = __int_as_float(e.y);
            uint2 u = __ldg(&Xh[(size_t)e.x * 32 + lane]);
            float2 f0 = __half22float2(*(const __half2*)&u.x);
            float2 f1 = __half22float2(*(const __half2*)&u.y);
            acc.x += f0.x * n; acc.y += f0.y * n;
            acc.z += f1.x * n; acc.w += f1.y * n;
        }
    }
    for (; j < end; j++) {
        int2 e = __ldg(&g_csr15[j]);
        float n = __int_as_float(e.y);
        uint2 u = __ldg(&Xh[(size_t)e.x * 32 + lane]);
        float2 f0 = __half22float2(*(const __half2*)&u.x);
        float2 f1 = __half22float2(*(const __half2*)&u.y);
        acc.x += f0.x * n; acc.y += f0.y * n;
        acc.z += f1.x * n; acc.w += f1.y * n;
    }
    uint2 o;
    *(__half2*)&o.x = __floats2half2_rn(acc.x * dd, acc.y * dd);
    *(__half2*)&o.y = __floats2half2_rn(acc.z * dd, acc.w * dd);
    ((uint2*)g_t1_16)[(size_t)gw * 32 + lane] = o;
}

// ---------------------------------------------------------------------------
// (6) agg2: t2 = A~ h1   (F=256 fp16 gather, fp32 accum, fp16 out)
// ---------------------------------------------------------------------------
__global__ void __launch_bounds__(256) k_agg2_15() {
    int gw = (blockIdx.x * 256 + threadIdx.x) >> 5;
    int lane = threadIdx.x & 31;
    if (gw >= N_NODES) return;
    int beg = __ldg(&g_rowptr15[gw]);
    int end = __ldg(&g_rowptr15[gw + 1]);
    float dd = __ldg(&g_dinv15[gw]);

    const uint4* Hh = (const uint4*)g_h1_16;
    float acc[8];
    {
        uint4 u = __ldg(&Hh[(size_t)gw * 32 + lane]);
        const __half2* h = (const __half2*)&u;
#pragma unroll
        for (int q = 0; q < 4; q++) {
            float2 f = __half22float2(h[q]);
            acc[q * 2 + 0] = f.x * dd;
            acc[q * 2 + 1] = f.y * dd;
        }
    }
    int j = beg;
    for (; j + 4 <= end; j += 4) {
#pragma unroll
        for (int u4 = 0; u4 < 4; u4++) {
            int2 e = __ldg(&g_csr15[j + u4]);
            float n = __int_as_float(e.y);
            uint4 u = __ldg(&Hh[(size_t)e.x * 32 + lane]);
            const __half2* h = (const __half2*)&u;
#pragma unroll
            for (int q = 0; q < 4; q++) {
                float2 f = __half22float2(h[q]);
                acc[q * 2 + 0] += f.x * n;
                acc[q * 2 + 1] += f.y * n;
            }
        }
    }
    for (; j < end; j++) {
        int2 e = __ldg(&g_csr15[j]);
        float n = __int_as_float(e.y);
        uint4 u = __ldg(&Hh[(size_t)e.x * 32 + lane]);
        const __half2* h = (const __half2*)&u;
#pragma unroll
        for (int q = 0; q < 4; q++) {
            float2 f = __half22float2(h[q]);
            acc[q * 2 + 0] += f.x * n;
            acc[q * 2 + 1] += f.y * n;
        }
    }
    uint4 o;
    __half2* oh = (__half2*)&o;
#pragma unroll
    for (int q = 0; q < 4; q++)
        oh[q] = __floats2half2_rn(acc[q * 2 + 0] * dd, acc[q * 2 + 1] * dd);
    ((uint4*)g_t2_16)[(size_t)gw * 32 + lane] = o;
}

// ---------------------------------------------------------------------------
// (5,7) fp16 tensor-core GEMM with ldmatrix fragment loads.
// BM=128 BN=128 BK=32, 256 threads = 8 warps (4M x 2N), warp tile 32x64.
//   LAYER 1: h1_16 = fp16(relu(t1 @ W1 + b1)), K=128
//   LAYER 2: relu(t2 @ W2 + b2) FUSED-POOLED into g_sums (no h2), K=256
// ---------------------------------------------------------------------------
template <int LAYER>
__global__ void __launch_bounds__(256) k_gemm15(const float* __restrict__ bias,
                                                const void* __restrict__ batch) {
    constexpr int K = (LAYER == 1) ? F_IN : HID;
    constexpr int BM = 128, BN = 128, BK = 32;
    constexpr int NT = K / BK;
    constexpr int STR = BK + 24;   // 56 halves = 112B row stride
    const __half* A  = (LAYER == 1) ? g_t1_16 : g_t2_16;
    const __half* Bt = (LAYER == 1) ? g_w1t : g_w2t;

    __shared__ __half As[2][BM][STR];
    __shared__ __half Bs[2][BN][STR];

    const int tid = threadIdx.x;
    const int wid = tid >> 5, lane = tid & 31;
    const int warpM = wid >> 1, warpN = wid & 1;
    const int row0 = blockIdx.y * BM, col0 = blockIdx.x * BN;
    const int gid = lane >> 2, tig = lane & 3;

    // ldmatrix lane-address components
    const int a_m = lane & 15;             // row within 16-row tile
    const int a_k = (lane >> 4) * 8;       // k-half select
    const int b_n = ((lane >> 4) << 3) | (lane & 7);   // row within 16-n pair
    const int b_k = ((lane >> 3) & 1) * 8;

    float c[2][8][4];
#pragma unroll
    for (int mt = 0; mt < 2; mt++)
#pragma unroll
        for (int nt = 0; nt < 8; nt++)
#pragma unroll
            for (int q = 0; q < 4; q++) c[mt][nt][q] = 0.0f;

    auto load_tile = [&](int buf, int k0) {
#pragma unroll
        for (int i = 0; i < 2; i++) {   // A: 128 rows x 4 chunks(8h)
            int idx = tid + i * 256;
            int m = idx >> 2, c8 = idx & 3;
            int gm = min(row0 + m, N_NODES - 1);
            cp_async16(&As[buf][m][c8 * 8], A + (size_t)gm * K + k0 + c8 * 8);
        }
#pragma unroll
        for (int i = 0; i < 2; i++) {   // B: 128 rows(n) x 4 chunks(8h)
            int idx = tid + i * 256;
            int n = idx >> 2, c8 = idx & 3;
            cp_async16(&Bs[buf][n][c8 * 8], Bt + (size_t)(col0 + n) * K + k0 + c8 * 8);
        }
        asm volatile("cp.async.commit_group;");
    };

    auto compute = [&](int buf) {
#pragma unroll
        for (int ks = 0; ks < 2; ks++) {
            const int k0 = ks * 16;
            uint32_t a[2][4];
#pragma unroll
            for (int mt = 0; mt < 2; mt++) {
                int m = warpM * 32 + mt * 16 + a_m;
                ldsm_x4(a[mt][0], a[mt][1], a[mt][2], a[mt][3],
                        smem_u32(&As[buf][m][k0 + a_k]));
            }
            uint32_t b[8][2];
#pragma unroll
            for (int ntp = 0; ntp < 4; ntp++) {
                int n = warpN * 64 + ntp * 16 + b_n;
                ldsm_x4(b[ntp * 2][0], b[ntp * 2][1],
                        b[ntp * 2 + 1][0], b[ntp * 2 + 1][1],
                        smem_u32(&Bs[buf][n][k0 + b_k]));
            }
#pragma unroll
            for (int mt = 0; mt < 2; mt++)
#pragma unroll
                for (int nt = 0; nt < 8; nt++)
                    mma_f16(c[mt][nt], a[mt], b[nt]);
        }
    };

    load_tile(0, 0);
    for (int t = 0; t < NT; t++) {
        if (t + 1 < NT) {
            load_tile((t + 1) & 1, (t + 1) * BK);
            asm volatile("cp.async.wait_group 1;");
        } else {
            asm volatile("cp.async.wait_group 0;");
        }
        __syncthreads();
        compute(t & 1);
        __syncthreads();
    }

    if (LAYER == 1) {
#pragma unroll
        for (int mt = 0; mt < 2; mt++) {
#pragma unroll
            for (int nt = 0; nt < 8; nt++) {
                int gn = col0 + warpN * 64 + nt * 8 + tig * 2;
                float b0 = __ldg(bias + gn), b1 = __ldg(bias + gn + 1);
                int r0 = row0 + warpM * 32 + mt * 16 + gid;
                int r1 = r0 + 8;
                if (r0 < N_NODES)
                    *(__half2*)(g_h1_16 + (size_t)r0 * HID + gn) =
                        __floats2half2_rn(fmaxf(c[mt][nt][0] + b0, 0.f),
                                          fmaxf(c[mt][nt][1] + b1, 0.f));
                if (r1 < N_NODES)
                    *(__half2*)(g_h1_16 + (size_t)r1 * HID + gn) =
                        __floats2half2_rn(fmaxf(c[mt][nt][2] + b0, 0.f),
                                          fmaxf(c[mt][nt][3] + b1, 0.f));
            }
        }
    } else {
        // fused mean-pool numerator: relu rows red.v2'ed into g_sums[graph]
        int is64 = g_is6415;
#pragma unroll
        for (int mt = 0; mt < 2; mt++) {
            int r0 = row0 + warpM * 32 + mt * 16 + gid;
            int r1 = r0 + 8;
            bool ok0 = r0 < N_NODES, ok1 = r1 < N_NODES;
            int g0 = ok0 ? idx_15(batch, r0, is64) : 0;
            int g1 = ok1 ? idx_15(batch, r1, is64) : 0;
#pragma unroll
            for (int nt = 0; nt < 8; nt++) {
                int gn = col0 + warpN * 64 + nt * 8 + tig * 2;
                float b0 = __ldg(bias + gn), b1 = __ldg(bias + gn + 1);
                float v00 = fmaxf(c[mt][nt][0] + b0, 0.f);
                float v01 = fmaxf(c[mt][nt][1] + b1, 0.f);
                float v10 = fmaxf(c[mt][nt][2] + b0, 0.f);
                float v11 = fmaxf(c[mt][nt][3] + b1, 0.f);
                if (ok0 && ok1 && g0 == g1) {
                    red_v2_15(g_sums15 + g0 * HID + gn, v00 + v10, v01 + v11);
                } else {
                    if (ok0) red_v2_15(g_sums15 + g0 * HID + gn, v00, v01);
                    if (ok1) red_v2_15(g_sums15 + g1 * HID + gn, v10, v11);
                }
            }
        }
    }
}

// ---------------------------------------------------------------------------
// (8) Final: mean, FC, log_softmax; re-zeros g_sums/g_cnt for next replay
// ---------------------------------------------------------------------------
__global__ void k_final15(const float* __restrict__ fcw, const float* __restrict__ fcb,
                          float* __restrict__ out) {
    int g = threadIdx.x;
    if (g >= N_GRAPHS) return;
    float cnt = g_cnt15[g];
    g_cnt15[g] = 0.0f;
    float inv = 1.0f / fmaxf(cnt, 1.0f);
    float l0 = fcb[0], l1 = fcb[1];
#pragma unroll 8
    for (int f = 0; f < HID; f++) {
        float p = g_sums15[g * HID + f] * inv;
        g_sums15[g * HID + f] = 0.0f;
        l0 += p * fcw[f * N_CLS + 0];
        l1 += p * fcw[f * N_CLS + 1];
    }
    float m = fmaxf(l0, l1);
    float lse = m + logf(expf(l0 - m) + expf(l1 - m));
    out[g * N_CLS + 0] = l0 - lse;
    out[g * N_CLS + 1] = l1 - lse;
}

// ---------------------------------------------------------------------------
extern "C" void kernel_launch(void* const* d_in, const int* in_sizes, int n_in,
                              void* d_out, int out_size) {
    const float* x     = (const float*)d_in[0];
    const void*  edges = d_in[1];
    const void*  batch = d_in[2];
    const float* W1    = (const float*)d_in[3];
    const float* b1    = (const float*)d_in[4];
    const float* W2    = (const float*)d_in[5];
    const float* b2    = (const float*)d_in[6];
    const float* fcw   = (const float*)d_in[7];
    const float* fcb   = (const float*)d_in[8];
    float* out = (float*)d_out;

    const int T = 256;
    dim3 gemm_grid(HID / 128, (N_NODES + 127) / 128);
    unsigned warps_grid = (unsigned)(((long long)N_NODES * 32 + 255) / 256);

    k_deg15<<<(N_EDGES + T - 1) / T, T>>>(edges, batch, x, W1, W2);  // 1
    k_scan15<<<1, 1024>>>();                                         // 2
    k_fill15<<<(N_EDGES + T - 1) / T, T>>>(edges);                   // 3
    k_agg1_15<<<warps_grid, 256>>>();                                // 4 <- profiled
    k_gemm15<1><<<gemm_grid, 256>>>(b1, batch);                      // 5
    k_agg2_15<<<warps_grid, 256>>>();                                // 6
    k_gemm15<2><<<gemm_grid, 256>>>(b2, batch);                      // 7 (+fused pool)
    k_final15<<<1, 64>>>(fcw, fcb, out);                             // 8
}

// round 17
// speedup vs baseline: 60.8900x; 1.0009x over previous
#include <cuda_runtime.h>
#include <cuda_fp16.h>
#include <cstdint>
#include <math.h>

#define N_NODES  100000
#define N_EDGES  3200000
#define N_GRAPHS 64
#define F_IN     128
#define HID      256
#define N_CLS    2

// ---------------------------------------------------------------------------
// Scratch — referenced ONLY from device code (GB300 ATS: host-side symbol
// references yield the host shadow; never pass these as kernel args).
// Zero-invariants: g_deg re-zeroed by k_fill; g_sums/g_cnt by k_final.
// ---------------------------------------------------------------------------
__device__ __align__(16) float  g_dinv17[N_NODES];
__device__ __align__(16) int    g_deg17[N_NODES];
__device__ __align__(16) int    g_rowptr17[N_NODES + 1];
__device__ __align__(16) int    g_cursor17[N_NODES];
__device__ __align__(16) int2   g_csr17[N_EDGES];                  // {src, dinv[src]}
__device__ __align__(16) __half g_x16[(size_t)N_NODES * F_IN];     // x fp16
__device__ __align__(16) __half g_t1_16[(size_t)N_NODES * F_IN];   // A~ x, fp16
__device__ __align__(16) __half g_h1_16[(size_t)N_NODES * HID];    // relu(t1 W1+b1), fp16
__device__ __align__(16) __half g_t2_16[(size_t)N_NODES * HID];    // A~ h1, fp16
__device__ __align__(16) __half g_w1t[HID * F_IN];                 // W1^T fp16 [n][k]
__device__ __align__(16) __half g_w2t[HID * HID];                  // W2^T fp16 [n][k]
__device__ __align__(16) float  g_sums17[N_GRAPHS * HID];
__device__ float g_cnt17[N_GRAPHS];
__device__ int   g_is6417;

// ---------------------------------------------------------------------------
__device__ __forceinline__ void red_v2_17(float* p, float a, float b) {
    asm volatile("red.global.add.v2.f32 [%0], {%1, %2};"
                 :: "l"(p), "f"(a), "f"(b) : "memory");
}
__device__ __forceinline__ int idx_17(const void* p, long long i, int is64) {
    return is64 ? (int)((const long long*)p)[i] : ((const int*)p)[i];
}
__device__ __forceinline__ void mma_f16(float c[4], const uint32_t a[4],
                                        const uint32_t b[2]) {
    asm volatile(
        "mma.sync.aligned.m16n8k16.row.col.f32.f16.f16.f32 "
        "{%0,%1,%2,%3}, {%4,%5,%6,%7}, {%8,%9}, {%0,%1,%2,%3};"
        : "+f"(c[0]), "+f"(c[1]), "+f"(c[2]), "+f"(c[3])
        : "r"(a[0]), "r"(a[1]), "r"(a[2]), "r"(a[3]), "r"(b[0]), "r"(b[1]));
}
__device__ __forceinline__ void ldsm_x4(uint32_t& r0, uint32_t& r1,
                                        uint32_t& r2, uint32_t& r3, uint32_t addr) {
    asm volatile("ldmatrix.sync.aligned.m8n8.x4.shared.b16 {%0,%1,%2,%3}, [%4];"
                 : "=r"(r0), "=r"(r1), "=r"(r2), "=r"(r3) : "r"(addr));
}
__device__ __forceinline__ uint32_t smem_u32(const void* p) {
    return (uint32_t)__cvta_generic_to_shared(p);
}
__device__ __forceinline__ void cp_async16(void* smem_dst, const void* gsrc) {
    uint32_t d = (uint32_t)__cvta_generic_to_shared(smem_dst);
    asm volatile("cp.async.cg.shared.global [%0], [%1], 16;" :: "r"(d), "l"(gsrc));
}
__device__ __forceinline__ int detect64_17(const void* edges) {
    const long long* p = (const long long*)edges;
    int ok = 1;
#pragma unroll
    for (int j = 0; j < 32; j++) {
        long long v = p[j];
        if (v < 0 || v >= N_NODES) ok = 0;
    }
    return ok;
}

// ---------------------------------------------------------------------------
// (1) degree + per-graph counts + x->fp16 + W1/W2 -> fp16 transposed + detect
// ---------------------------------------------------------------------------
__global__ void k_deg17(const void* __restrict__ edges,
                        const void* __restrict__ batch,
                        const float* __restrict__ X,
                        const float* __restrict__ W1,
                        const float* __restrict__ W2) {
    __shared__ int s_is64;
    if (threadIdx.x == 0) {
        int v = detect64_17(edges);
        s_is64 = v;
        if (blockIdx.x == 0) g_is6417 = v;
    }
    __syncthreads();
    int is64 = s_is64;
    int i = blockIdx.x * blockDim.x + threadIdx.x;
    if (i < N_NODES * (F_IN / 4)) {      // x -> fp16 (vectorized)
        float4 v = ((const float4*)X)[i];
        ((__half2*)g_x16)[i * 2 + 0] = __floats2half2_rn(v.x, v.y);
        ((__half2*)g_x16)[i * 2 + 1] = __floats2half2_rn(v.z, v.w);
    }
    if (i < HID * F_IN) {                // W1^T: w1t[n*128+k] = W1[k*256+n]
        int n = i >> 7, k = i & 127;
        g_w1t[i] = __float2half_rn(W1[(size_t)k * HID + n]);
    }
    if (i < HID * HID) {                 // W2^T: w2t[n*256+k] = W2[k*256+n]
        int n = i >> 8, k = i & 255;
        g_w2t[i] = __float2half_rn(W2[(size_t)k * HID + n]);
    }
    if (i < N_EDGES) {
        int d = idx_17(edges, (long long)N_EDGES + i, is64);
        atomicAdd(&g_deg17[d], 1);
    }
    if (i < N_NODES) {
        int g = idx_17(batch, i, is64);
        atomicAdd(&g_cnt17[g], 1.0f);
    }
}

// (2) single-block scan -> rowptr/cursor; dinv = rsqrt(deg+1)
__global__ void k_scan17() {
    const int T = 1024;
    const int CH = (N_NODES + T - 1) / T;
    __shared__ int part[T];
    int t = threadIdx.x;
    int base = t * CH;
    int local = 0;
    for (int i = 0; i < CH; i++) {
        int idx = base + i;
        if (idx < N_NODES) local += g_deg17[idx];
    }
    part[t] = local;
    __syncthreads();
    for (int off = 1; off < T; off <<= 1) {
        int v = (t >= off) ? part[t - off] : 0;
        __syncthreads();
        if (t >= off) part[t] += v;
        __syncthreads();
    }
    int prefix = (t == 0) ? 0 : part[t - 1];
    for (int i = 0; i < CH; i++) {
        int idx = base + i;
        if (idx < N_NODES) {
            g_rowptr17[idx] = prefix;
            g_cursor17[idx] = prefix;
            prefix += g_deg17[idx];
        }
    }
    if (t == T - 1) g_rowptr17[N_NODES] = part[T - 1];
    __syncthreads();
    for (int i = t; i < N_NODES; i += T)
        g_dinv17[i] = rsqrtf((float)(g_deg17[i] + 1));
}

// (3) CSR fill {src, dinv[src]}; re-zeros g_deg for next replay
__global__ void k_fill17(const void* __restrict__ edges) {
    int e = blockIdx.x * blockDim.x + threadIdx.x;
    if (e < N_NODES) g_deg17[e] = 0;
    if (e >= N_EDGES) return;
    int is64 = g_is6417;
    int s = idx_17(edges, e, is64);
    int d = idx_17(edges, (long long)N_EDGES + e, is64);
    int slot = atomicAdd(&g_cursor17[d], 1);
    g_csr17[slot] = make_int2(s, __float_as_int(g_dinv17[s]));
}

// ---------------------------------------------------------------------------
// (4) agg1: t1 = A~ x   (F=128 fp16 gather, fp32 accum, fp16 out)
// ---------------------------------------------------------------------------
__global__ void __launch_bounds__(256) k_agg1_17() {
    int gw = (blockIdx.x * 256 + threadIdx.x) >> 5;
    int lane = threadIdx.x & 31;
    if (gw >= N_NODES) return;
    int beg = __ldg(&g_rowptr17[gw]);
    int end = __ldg(&g_rowptr17[gw + 1]);
    float dd = __ldg(&g_dinv17[gw]);

    const uint2* Xh = (const uint2*)g_x16;
    float4 acc;
    {
        uint2 u = __ldg(&Xh[(size_t)gw * 32 + lane]);
        float2 f0 = __half22float2(*(const __half2*)&u.x);
        float2 f1 = __half22float2(*(const __half2*)&u.y);
        acc = make_float4(f0.x * dd, f0.y * dd, f1.x * dd, f1.y * dd);
    }
    int j = beg;
    for (; j + 8 <= end; j += 8) {
#pragma unroll
        for (int u8 = 0; u8 < 8; u8++) {
            int2 e = __ldg(&g_csr17[j + u8]);
            float n = __int_as_float(e.y);
            uint2 u = __ldg(&Xh[(size_t)e.x * 32 + lane]);
            float2 f0 = __half22float2(*(const __half2*)&u.x);
            float2 f1 = __half22float2(*(const __half2*)&u.y);
            acc.x += f0.x * n; acc.y += f0.y * n;
            acc.z += f1.x * n; acc.w += f1.y * n;
        }
    }
    for (; j < end; j++) {
        int2 e = __ldg(&g_csr17[j]);
        float n = __int_as_float(e.y);
        uint2 u = __ldg(&Xh[(size_t)e.x * 32 + lane]);
        float2 f0 = __half22float2(*(const __half2*)&u.x);
        float2 f1 = __half22float2(*(const __half2*)&u.y);
        acc.x += f0.x * n; acc.y += f0.y * n;
        acc.z += f1.x * n; acc.w += f1.y * n;
    }
    uint2 o;
    *(__half2*)&o.x = __floats2half2_rn(acc.x * dd, acc.y * dd);
    *(__half2*)&o.y = __floats2half2_rn(acc.z * dd, acc.w * dd);
    ((uint2*)g_t1_16)[(size_t)gw * 32 + lane] = o;
}

// ---------------------------------------------------------------------------
// (6) agg2: t2 = A~ h1   (F=256 fp16 gather, fp32 accum, fp16 out)
// ---------------------------------------------------------------------------
__global__ void __launch_bounds__(256) k_agg2_17() {
    int gw = (blockIdx.x * 256 + threadIdx.x) >> 5;
    int lane = threadIdx.x & 31;
    if (gw >= N_NODES) return;
    int beg = __ldg(&g_rowptr17[gw]);
    int end = __ldg(&g_rowptr17[gw + 1]);
    float dd = __ldg(&g_dinv17[gw]);

    const uint4* Hh = (const uint4*)g_h1_16;
    float acc[8];
    {
        uint4 u = __ldg(&Hh[(size_t)gw * 32 + lane]);
        const __half2* h = (const __half2*)&u;
#pragma unroll
        for (int q = 0; q < 4; q++) {
            float2 f = __half22float2(h[q]);
            acc[q * 2 + 0] = f.x * dd;
            acc[q * 2 + 1] = f.y * dd;
        }
    }
    int j = beg;
    for (; j + 4 <= end; j += 4) {
#pragma unroll
        for (int u4 = 0; u4 < 4; u4++) {
            int2 e = __ldg(&g_csr17[j + u4]);
            float n = __int_as_float(e.y);
            uint4 u = __ldg(&Hh[(size_t)e.x * 32 + lane]);
            const __half2* h = (const __half2*)&u;
#pragma unroll
            for (int q = 0; q < 4; q++) {
                float2 f = __half22float2(h[q]);
                acc[q * 2 + 0] += f.x * n;
                acc[q * 2 + 1] += f.y * n;
            }
        }
    }
    for (; j < end; j++) {
        int2 e = __ldg(&g_csr17[j]);
        float n = __int_as_float(e.y);
        uint4 u = __ldg(&Hh[(size_t)e.x * 32 + lane]);
        const __half2* h = (const __half2*)&u;
#pragma unroll
        for (int q = 0; q < 4; q++) {
            float2 f = __half22float2(h[q]);
            acc[q * 2 + 0] += f.x * n;
            acc[q * 2 + 1] += f.y * n;
        }
    }
    uint4 o;
    __half2* oh = (__half2*)&o;
#pragma unroll
    for (int q = 0; q < 4; q++)
        oh[q] = __floats2half2_rn(acc[q * 2 + 0] * dd, acc[q * 2 + 1] * dd);
    ((uint4*)g_t2_16)[(size_t)gw * 32 + lane] = o;
}

// ---------------------------------------------------------------------------
// (5,7) fp16 tensor-core GEMM, ldmatrix frags, 3-STAGE cp.async pipeline.
// Tail fix: last iteration must wait_group 0 (its own group is the youngest).
// BM=128 BN=128 BK=32, 256 threads = 8 warps (4M x 2N), warp tile 32x64.
//   LAYER 1: h1_16 = fp16(relu(t1 @ W1 + b1)), K=128
//   LAYER 2: relu(t2 @ W2 + b2) FUSED-POOLED into g_sums (no h2), K=256
// ---------------------------------------------------------------------------
template <int LAYER>
__global__ void __launch_bounds__(256) k_gemm17(const float* __restrict__ bias,
                                                const void* __restrict__ batch) {
    constexpr int K = (LAYER == 1) ? F_IN : HID;
    constexpr int BM = 128, BN = 128, BK = 32;
    constexpr int NT = K / BK;           // 4 or 8 (>= 2)
    constexpr int STR = BK + 8;          // 40 halves = 80B row: conflict-free ldsm
    const __half* A  = (LAYER == 1) ? g_t1_16 : g_t2_16;
    const __half* Bt = (LAYER == 1) ? g_w1t : g_w2t;

    __shared__ __half As[3][BM][STR];
    __shared__ __half Bs[3][BN][STR];

    const int tid = threadIdx.x;
    const int wid = tid >> 5, lane = tid & 31;
    const int warpM = wid >> 1, warpN = wid & 1;
    const int row0 = blockIdx.y * BM, col0 = blockIdx.x * BN;
    const int gid = lane >> 2, tig = lane & 3;

    // ldmatrix lane-address components
    const int a_m = lane & 15;
    const int a_k = (lane >> 4) * 8;
    const int b_n = ((lane >> 4) << 3) | (lane & 7);
    const int b_k = ((lane >> 3) & 1) * 8;

    float c[2][8][4];
#pragma unroll
    for (int mt = 0; mt < 2; mt++)
#pragma unroll
        for (int nt = 0; nt < 8; nt++)
#pragma unroll
            for (int q = 0; q < 4; q++) c[mt][nt][q] = 0.0f;

    auto load_tile = [&](int buf, int k0) {
#pragma unroll
        for (int i = 0; i < 2; i++) {   // A: 128 rows x 4 chunks(8h)
            int idx = tid + i * 256;
            int m = idx >> 2, c8 = idx & 3;
            int gm = min(row0 + m, N_NODES - 1);
            cp_async16(&As[buf][m][c8 * 8], A + (size_t)gm * K + k0 + c8 * 8);
        }
#pragma unroll
        for (int i = 0; i < 2; i++) {   // B: 128 rows(n) x 4 chunks(8h)
            int idx = tid + i * 256;
            int n = idx >> 2, c8 = idx & 3;
            cp_async16(&Bs[buf][n][c8 * 8], Bt + (size_t)(col0 + n) * K + k0 + c8 * 8);
        }
        asm volatile("cp.async.commit_group;");
    };

    auto compute = [&](int buf) {
#pragma unroll
        for (int ks = 0; ks < 2; ks++) {
            const int k0 = ks * 16;
            uint32_t a[2][4];
#pragma unroll
            for (int mt = 0; mt < 2; mt++) {
                int m = warpM * 32 + mt * 16 + a_m;
                ldsm_x4(a[mt][0], a[mt][1], a[mt][2], a[mt][3],
                        smem_u32(&As[buf][m][k0 + a_k]));
            }
            uint32_t b[8][2];
#pragma unroll
            for (int ntp = 0; ntp < 4; ntp++) {
                int n = warpN * 64 + ntp * 16 + b_n;
                ldsm_x4(b[ntp * 2][0], b[ntp * 2][1],
                        b[ntp * 2 + 1][0], b[ntp * 2 + 1][1],
                        smem_u32(&Bs[buf][n][k0 + b_k]));
            }
#pragma unroll
            for (int mt = 0; mt < 2; mt++)
#pragma unroll
                for (int nt = 0; nt < 8; nt++)
                    mma_f16(c[mt][nt], a[mt], b[nt]);
        }
    };

    // 3-stage pipeline: 2 tiles in flight ahead of compute
    load_tile(0, 0);
    load_tile(1, BK);
    for (int t = 0; t < NT; t++) {
        if (t + 1 < NT) {
            asm volatile("cp.async.wait_group 1;");   // group t complete (younger pending)
        } else {
            asm volatile("cp.async.wait_group 0;");   // TAIL: group t is the youngest
        }
        __syncthreads();                              // visible to all warps
        if (t + 2 < NT) load_tile((t + 2) % 3, (t + 2) * BK);
        compute(t % 3);
        __syncthreads();                              // done reading before overwrite
    }

    if (LAYER == 1) {
#pragma unroll
        for (int mt = 0; mt < 2; mt++) {
#pragma unroll
            for (int nt = 0; nt < 8; nt++) {
                int gn = col0 + warpN * 64 + nt * 8 + tig * 2;
                float b0 = __ldg(bias + gn), b1 = __ldg(bias + gn + 1);
                int r0 = row0 + warpM * 32 + mt * 16 + gid;
                int r1 = r0 + 8;
                if (r0 < N_NODES)
                    *(__half2*)(g_h1_16 + (size_t)r0 * HID + gn) =
                        __floats2half2_rn(fmaxf(c[mt][nt][0] + b0, 0.f),
                                          fmaxf(c[mt][nt][1] + b1, 0.f));
                if (r1 < N_NODES)
                    *(__half2*)(g_h1_16 + (size_t)r1 * HID + gn) =
                        __floats2half2_rn(fmaxf(c[mt][nt][2] + b0, 0.f),
                                          fmaxf(c[mt][nt][3] + b1, 0.f));
            }
        }
    } else {
        // fused mean-pool numerator: relu rows red.v2'ed into g_sums[graph]
        int is64 = g_is6417;
#pragma unroll
        for (int mt = 0; mt < 2; mt++) {
            int r0 = row0 + warpM * 32 + mt * 16 + gid;
            int r1 = r0 + 8;
            bool ok0 = r0 < N_NODES, ok1 = r1 < N_NODES;
            int g0 = ok0 ? idx_17(batch, r0, is64) : 0;
            int g1 = ok1 ? idx_17(batch, r1, is64) : 0;
#pragma unroll
            for (int nt = 0; nt < 8; nt++) {
                int gn = col0 + warpN * 64 + nt * 8 + tig * 2;
                float b0 = __ldg(bias + gn), b1 = __ldg(bias + gn + 1);
                float v00 = fmaxf(c[mt][nt][0] + b0, 0.f);
                float v01 = fmaxf(c[mt][nt][1] + b1, 0.f);
                float v10 = fmaxf(c[mt][nt][2] + b0, 0.f);
                float v11 = fmaxf(c[mt][nt][3] + b1, 0.f);
                if (ok0 && ok1 && g0 == g1) {
                    red_v2_17(g_sums17 + g0 * HID + gn, v00 + v10, v01 + v11);
                } else {
                    if (ok0) red_v2_17(g_sums17 + g0 * HID + gn, v00, v01);
                    if (ok1) red_v2_17(g_sums17 + g1 * HID + gn, v10, v11);
                }
            }
        }
    }
}

// ---------------------------------------------------------------------------
// (8) Final: mean, FC, log_softmax; re-zeros g_sums/g_cnt for next replay
// ---------------------------------------------------------------------------
__global__ void k_final17(const float* __restrict__ fcw, const float* __restrict__ fcb,
                          float* __restrict__ out) {
    int g = threadIdx.x;
    if (g >= N_GRAPHS) return;
    float cnt = g_cnt17[g];
    g_cnt17[g] = 0.0f;
    float inv = 1.0f / fmaxf(cnt, 1.0f);
    float l0 = fcb[0], l1 = fcb[1];
#pragma unroll 8
    for (int f = 0; f < HID; f++) {
        float p = g_sums17[g * HID + f] * inv;
        g_sums17[g * HID + f] = 0.0f;
        l0 += p * fcw[f * N_CLS + 0];
        l1 += p * fcw[f * N_CLS + 1];
    }
    float m = fmaxf(l0, l1);
    float lse = m + logf(expf(l0 - m) + expf(l1 - m));
    out[g * N_CLS + 0] = l0 - lse;
    out[g * N_CLS + 1] = l1 - lse;
}

// ---------------------------------------------------------------------------
extern "C" void kernel_launch(void* const* d_in, const int* in_sizes, int n_in,
                              void* d_out, int out_size) {
    const float* x     = (const float*)d_in[0];
    const void*  edges = d_in[1];
    const void*  batch = d_in[2];
    const float* W1    = (const float*)d_in[3];
    const float* b1    = (const float*)d_in[4];
    const float* W2    = (const float*)d_in[5];
    const float* b2    = (const float*)d_in[6];
    const float* fcw   = (const float*)d_in[7];
    const float* fcb   = (const float*)d_in[8];
    float* out = (float*)d_out;

    const int T = 256;
    dim3 gemm_grid(HID / 128, (N_NODES + 127) / 128);
    unsigned warps_grid = (unsigned)(((long long)N_NODES * 32 + 255) / 256);

    k_deg17<<<(N_EDGES + T - 1) / T, T>>>(edges, batch, x, W1, W2);  // 1
    k_scan17<<<1, 1024>>>();                                         // 2
    k_fill17<<<(N_EDGES + T - 1) / T, T>>>(edges);                   // 3
    k_agg1_17<<<warps_grid, 256>>>();                                // 4 <- profiled
    k_gemm17<1><<<gemm_grid, 256>>>(b1, batch);                      // 5
    k_agg2_17<<<warps_grid, 256>>>();                                // 6
    k_gemm17<2><<<gemm_grid, 256>>>(b2, batch);                      // 7 (+fused pool)
    k_final17<<<1, 64>>>(fcw, fcb, out);                             // 8
}